// round 2
// baseline (speedup 1.0000x reference)
#include <cuda_runtime.h>
#include <cstdint>

// Problem constants (fixed shapes for this dataset)
#define NNODES   50000
#define DFEAT    256
#define H1HEADS  4
#define HD1      64
#define NGRAPHS  8
#define EMAX     400000
#define ETOTMAX  (EMAX + NNODES)

// ---------------- scratch (static device globals; no allocation) ----------------
__device__ float g_bufA[NNODES * DFEAT];   // linear-layer output (h1 / h2)
__device__ float g_bufB[NNODES * DFEAT];   // aggregation output / BN in-place
__device__ float g_als1[NNODES * H1HEADS];
__device__ float g_ald1[NNODES * H1HEADS];
__device__ float g_als2[NNODES];
__device__ float g_ald2[NNODES];
__device__ float g_p1[(size_t)ETOTMAX * H1HEADS];
__device__ float g_p2[ETOTMAX];
__device__ float g_den1[NNODES * H1HEADS];
__device__ float g_den2[NNODES];
__device__ float g_bn_sum[DFEAT];
__device__ float g_bn_sumsq[DFEAT];
__device__ float g_pool_sum[NGRAPHS * DFEAT];
__device__ float g_pool_cnt[NGRAPHS];
__device__ float g_s2[NGRAPHS];

// ---------------- helpers ----------------
__device__ __forceinline__ void red4(float* a, float x, float y, float z, float w) {
    asm volatile("red.global.add.v4.f32 [%0], {%1,%2,%3,%4};"
                 :: "l"(a), "f"(x), "f"(y), "f"(z), "f"(w) : "memory");
}

// ---------------- SGEMM: C[M,Nn] = A[M,K] @ B[K,Nn], row-major fp32 ----------------
#define BM 128
#define BN 64
#define BK 16
__global__ __launch_bounds__(256) void sgemm_k(const float* __restrict__ A,
                                               const float* __restrict__ B,
                                               float* __restrict__ C,
                                               int M, int K, int Nn) {
    __shared__ float As[BK][BM + 4];
    __shared__ float Bs[BK][BN];
    int t  = threadIdx.x;
    int m0 = blockIdx.y * BM;
    int n0 = blockIdx.x * BN;
    int tx = t & 15;   // column group (x4)
    int ty = t >> 4;   // row group (x8)
    float acc[8][4];
#pragma unroll
    for (int i = 0; i < 8; i++)
#pragma unroll
        for (int j = 0; j < 4; j++) acc[i][j] = 0.f;

    for (int k0 = 0; k0 < K; k0 += BK) {
        // A tile: 128x16 (512 float4 loads, 2 per thread), stored transposed
#pragma unroll
        for (int i = 0; i < 2; i++) {
            int f  = t + i * 256;
            int r  = f >> 2;
            int c4 = (f & 3) * 4;
            int gm = m0 + r;
            float4 v = make_float4(0.f, 0.f, 0.f, 0.f);
            if (gm < M) v = *(const float4*)(A + (size_t)gm * K + k0 + c4);
            As[c4 + 0][r] = v.x; As[c4 + 1][r] = v.y;
            As[c4 + 2][r] = v.z; As[c4 + 3][r] = v.w;
        }
        // B tile: 16x64 (256 float4 loads, 1 per thread)
        {
            int r  = t >> 4;
            int c4 = (t & 15) * 4;
            float4 v = *(const float4*)(B + (size_t)(k0 + r) * Nn + n0 + c4);
            *(float4*)&Bs[r][c4] = v;
        }
        __syncthreads();
#pragma unroll
        for (int k = 0; k < BK; k++) {
            float a_[8];
#pragma unroll
            for (int i = 0; i < 8; i++) a_[i] = As[k][ty * 8 + i];
            float4 b4 = *(float4*)&Bs[k][tx * 4];
            float b_[4] = {b4.x, b4.y, b4.z, b4.w};
#pragma unroll
            for (int i = 0; i < 8; i++)
#pragma unroll
                for (int j = 0; j < 4; j++) acc[i][j] += a_[i] * b_[j];
        }
        __syncthreads();
    }
#pragma unroll
    for (int i = 0; i < 8; i++) {
        int gm = m0 + ty * 8 + i;
        if (gm < M) {
            float4 v = make_float4(acc[i][0], acc[i][1], acc[i][2], acc[i][3]);
            *(float4*)(C + (size_t)gm * Nn + n0 + tx * 4) = v;
        }
    }
}

// ---------------- attention logits per node ----------------
__global__ void al1_k(const float* __restrict__ h, const float* __restrict__ a_src,
                      const float* __restrict__ a_dst, float* als, float* ald, int N) {
    int i = blockIdx.x * 256 + threadIdx.x;
    if (i >= N * H1HEADS) return;
    int n = i >> 2, hh = i & 3;
    const float* row = h + (size_t)n * DFEAT + hh * HD1;
    const float* as  = a_src + hh * HD1;
    const float* ad  = a_dst + hh * HD1;
    float s = 0.f, d = 0.f;
#pragma unroll
    for (int c = 0; c < HD1; c++) { float v = row[c]; s += v * as[c]; d += v * ad[c]; }
    als[i] = s; ald[i] = d;
}

__global__ void al2_k(const float* __restrict__ h, const float* __restrict__ a_src,
                      const float* __restrict__ a_dst, float* als, float* ald, int N) {
    int w    = (blockIdx.x * blockDim.x + threadIdx.x) >> 5;
    int lane = threadIdx.x & 31;
    if (w >= N) return;
    const float* row = h + (size_t)w * DFEAT;
    float s = 0.f, d = 0.f;
#pragma unroll
    for (int j = 0; j < 8; j++) {
        int c = lane + j * 32;
        float v = row[c];
        s += v * a_src[c]; d += v * a_dst[c];
    }
#pragma unroll
    for (int o = 16; o; o >>= 1) {
        s += __shfl_down_sync(0xffffffffu, s, o);
        d += __shfl_down_sync(0xffffffffu, d, o);
    }
    if (!lane) { als[w] = s; ald[w] = d; }
}

// ---------------- edge softmax denominator (no max-shift; bounded logits) ----------------
template <int H>
__global__ void att_denom_k(const int* __restrict__ ei, int E, int N,
                            const float* __restrict__ als, const float* __restrict__ ald,
                            float* __restrict__ p, float* __restrict__ den) {
    int e = blockIdx.x * 256 + threadIdx.x;
    int Etot = E + N;
    if (e >= Etot) return;
    int s, d;
    if (e < E) { s = ei[e]; d = ei[E + e]; } else { s = d = e - E; }
#pragma unroll
    for (int h = 0; h < H; h++) {
        float v = als[s * H + h] + ald[d * H + h];
        v = v > 0.f ? v : 0.2f * v;          // leaky_relu 0.2
        float pe = expf(v);
        p[(size_t)e * H + h] = pe;
        atomicAdd(&den[d * H + h], pe);
    }
}

// ---------------- scatter: out[dst] += h[src] * alpha  (warp per edge) ----------------
template <int H>
__global__ void scatter_k(const int* __restrict__ ei, int E, int N,
                          const float* __restrict__ h, const float* __restrict__ p,
                          const float* __restrict__ den, float* __restrict__ out) {
    int w    = (blockIdx.x * blockDim.x + threadIdx.x) >> 5;
    int lane = threadIdx.x & 31;
    int Etot = E + N;
    if (w >= Etot) return;
    int s, d;
    if (w < E) { s = ei[w]; d = ei[E + w]; } else { s = d = w - E; }
    int c0   = lane * 8;
    int head = (H == 4) ? (c0 >> 6) : 0;
    float alpha = p[(size_t)w * H + head] / (den[d * H + head] + 1e-16f);
    const float4* hs = (const float4*)(h + (size_t)s * DFEAT + c0);
    float4 v0 = hs[0], v1 = hs[1];
    float* ob = out + (size_t)d * DFEAT + c0;
    red4(ob,     v0.x * alpha, v0.y * alpha, v0.z * alpha, v0.w * alpha);
    red4(ob + 4, v1.x * alpha, v1.y * alpha, v1.z * alpha, v1.w * alpha);
}

// ---------------- BatchNorm (training mode, biased var) ----------------
__global__ void bn_stats_k(const float* __restrict__ x, int N, float* sum, float* sumsq) {
    int c  = threadIdx.x;            // 256 = channel
    int n0 = blockIdx.x * 256;
    int n1 = min(n0 + 256, N);
    float s = 0.f, q = 0.f;
    for (int n = n0; n < n1; n++) {
        float v = x[(size_t)n * DFEAT + c];
        s += v; q += v * v;
    }
    atomicAdd(&sum[c], s);
    atomicAdd(&sumsq[c], q);
}

__global__ void bn_apply_k(float* __restrict__ x, int N,
                           const float* __restrict__ sum, const float* __restrict__ sumsq,
                           const float* __restrict__ g, const float* __restrict__ be) {
    int i = blockIdx.x * 256 + threadIdx.x;
    if (i >= N * DFEAT) return;
    int c = i & 255;
    float invN = 1.f / (float)N;
    float m = sum[c] * invN;
    float v = sumsq[c] * invN - m * m;
    float y = (x[i] - m) * rsqrtf(v + 1e-5f) * g[c] + be[c];
    x[i] = fmaxf(y, 0.f);
}

// ---------------- global mean pool (batch_index sorted) ----------------
__global__ void pool_k(const float* __restrict__ x, const int* __restrict__ batch,
                       int N, float* sums, float* cnt) {
    int c  = threadIdx.x;  // 256
    int n0 = blockIdx.x * 256;
    if (n0 >= N) return;
    int n1  = min(n0 + 256, N);
    int cur = batch[n0];
    float acc = 0.f, cacc = 0.f;
    for (int n = n0; n < n1; n++) {
        int gq = batch[n];
        if (gq != cur) {
            atomicAdd(&sums[cur * DFEAT + c], acc); acc = 0.f;
            if (c == 0) { atomicAdd(&cnt[cur], cacc); cacc = 0.f; }
            cur = gq;
        }
        acc  += x[(size_t)n * DFEAT + c];
        cacc += 1.f;
    }
    atomicAdd(&sums[cur * DFEAT + c], acc);
    if (c == 0) atomicAdd(&cnt[cur], cacc);
}

// ---------------- small heads: shared MLP, s2 precompute, type_logits, value ----------------
__global__ void heads_k(const float* __restrict__ xn, const int* __restrict__ target,
                        const float* __restrict__ Wsh, const float* __restrict__ bsh,
                        const float* __restrict__ Wnode,
                        const float* __restrict__ Wtype, const float* __restrict__ btype,
                        const float* __restrict__ Wcrit, const float* __restrict__ bcrit,
                        const float* __restrict__ pool_sums, const float* __restrict__ pool_cnt,
                        float* __restrict__ s2, float* __restrict__ out, int N) {
    __shared__ float gf[NGRAPHS][DFEAT];
    __shared__ float sh[NGRAPHS][DFEAT];
    int t = threadIdx.x;  // 256
    for (int b = 0; b < NGRAPHS; b++)
        gf[b][t] = pool_sums[b * DFEAT + t] / fmaxf(pool_cnt[b], 1.f);
    __syncthreads();
    for (int b = 0; b < NGRAPHS; b++) {
        float acc = bsh[t];
        for (int k = 0; k < DFEAT; k++) acc += gf[b][k] * Wsh[k * DFEAT + t];
        sh[b][t] = fmaxf(acc, 0.f);
    }
    __syncthreads();
    // s2[b] = shared[b] . W_node[256:512]
    {
        int wq = t >> 5, lane = t & 31;  // warp w handles graph w (8 warps)
        float a = 0.f;
#pragma unroll
        for (int j = 0; j < 8; j++) { int c = lane + j * 32; a += sh[wq][c] * Wnode[256 + c]; }
#pragma unroll
        for (int o = 16; o; o >>= 1) a += __shfl_down_sync(0xffffffffu, a, o);
        if (!lane) s2[wq] = a;
    }
    // type_logits[b][a]
    if (t < 32) {
        int b = t >> 2, aa = t & 3;
        int tn = target[b];
        float acc = btype[aa];
        for (int c = 0; c < DFEAT; c++) acc += sh[b][c] * Wtype[c * 4 + aa];
        for (int c = 0; c < DFEAT; c++) acc += xn[(size_t)tn * DFEAT + c] * Wtype[(256 + c) * 4 + aa];
        out[N + t] = acc;
    }
    // value[b]
    if (t >= 64 && t < 64 + NGRAPHS) {
        int b = t - 64;
        float acc = bcrit[0];
        for (int c = 0; c < DFEAT; c++) acc += sh[b][c] * Wcrit[c];
        out[N + 32 + b] = acc;
    }
}

// ---------------- node scores: warp per node ----------------
__global__ void nodescore_k(const float* __restrict__ xn, const int* __restrict__ batch,
                            const float* __restrict__ Wnode, const float* __restrict__ bnode,
                            const float* __restrict__ s2, float* __restrict__ out, int N) {
    int w    = (blockIdx.x * blockDim.x + threadIdx.x) >> 5;
    int lane = threadIdx.x & 31;
    if (w >= N) return;
    const float* row = xn + (size_t)w * DFEAT;
    float a = 0.f;
#pragma unroll
    for (int j = 0; j < 8; j++) { int c = lane + j * 32; a += row[c] * Wnode[c]; }
#pragma unroll
    for (int o = 16; o; o >>= 1) a += __shfl_down_sync(0xffffffffu, a, o);
    if (!lane) out[w] = a + s2[batch[w]] + bnode[0];
}

// ---------------- host orchestration ----------------
static inline int cdiv(int a, int b) { return (a + b - 1) / b; }

extern "C" void kernel_launch(void* const* d_in, const int* in_sizes, int n_in,
                              void* d_out, int out_size) {
    const float* x      = (const float*)d_in[0];
    const int*   ei     = (const int*)d_in[1];
    const int*   batch  = (const int*)d_in[2];
    const int*   target = (const int*)d_in[3];
    const float* W1     = (const float*)d_in[4];
    const float* a1s    = (const float*)d_in[5];
    const float* a1d    = (const float*)d_in[6];
    const float* W2     = (const float*)d_in[8];
    const float* a2s    = (const float*)d_in[9];
    const float* a2d    = (const float*)d_in[10];
    const float* g1     = (const float*)d_in[12];
    const float* be1    = (const float*)d_in[13];
    const float* g2     = (const float*)d_in[14];
    const float* be2    = (const float*)d_in[15];
    const float* Wsh    = (const float*)d_in[16];
    const float* bsh    = (const float*)d_in[17];
    const float* Wnode  = (const float*)d_in[18];
    const float* bnode  = (const float*)d_in[19];
    const float* Wtype  = (const float*)d_in[20];
    const float* btype  = (const float*)d_in[21];
    const float* Wcrit  = (const float*)d_in[22];
    const float* bcrit  = (const float*)d_in[23];
    float* out = (float*)d_out;

    int N = in_sizes[2];
    int F = in_sizes[0] / N;
    int E = in_sizes[1] / 2;
    int Etot = E + N;

    float *bufA, *bufB, *als1, *ald1, *als2, *ald2, *p1, *p2, *den1, *den2;
    float *bnS, *bnQ, *poolS, *poolC, *s2;
    cudaGetSymbolAddress((void**)&bufA,  g_bufA);
    cudaGetSymbolAddress((void**)&bufB,  g_bufB);
    cudaGetSymbolAddress((void**)&als1,  g_als1);
    cudaGetSymbolAddress((void**)&ald1,  g_ald1);
    cudaGetSymbolAddress((void**)&als2,  g_als2);
    cudaGetSymbolAddress((void**)&ald2,  g_ald2);
    cudaGetSymbolAddress((void**)&p1,    g_p1);
    cudaGetSymbolAddress((void**)&p2,    g_p2);
    cudaGetSymbolAddress((void**)&den1,  g_den1);
    cudaGetSymbolAddress((void**)&den2,  g_den2);
    cudaGetSymbolAddress((void**)&bnS,   g_bn_sum);
    cudaGetSymbolAddress((void**)&bnQ,   g_bn_sumsq);
    cudaGetSymbolAddress((void**)&poolS, g_pool_sum);
    cudaGetSymbolAddress((void**)&poolC, g_pool_cnt);
    cudaGetSymbolAddress((void**)&s2,    g_s2);

    // ---- zero init (async memsets; graph-capturable) ----
    cudaMemsetAsync(den1,  0, (size_t)N * H1HEADS * sizeof(float));
    cudaMemsetAsync(den2,  0, (size_t)N * sizeof(float));
    cudaMemsetAsync(bufB,  0, (size_t)N * DFEAT * sizeof(float));
    cudaMemsetAsync(poolS, 0, NGRAPHS * DFEAT * sizeof(float));
    cudaMemsetAsync(poolC, 0, NGRAPHS * sizeof(float));
    cudaMemsetAsync(bnS,   0, DFEAT * sizeof(float));
    cudaMemsetAsync(bnQ,   0, DFEAT * sizeof(float));

    // ---- GAT layer 1 ----
    {
        dim3 grid(DFEAT / BN, cdiv(N, BM));
        sgemm_k<<<grid, 256>>>(x, W1, bufA, N, F, DFEAT);
    }
    al1_k<<<cdiv(N * H1HEADS, 256), 256>>>(bufA, a1s, a1d, als1, ald1, N);
    att_denom_k<H1HEADS><<<cdiv(Etot, 256), 256>>>(ei, E, N, als1, ald1, p1, den1);
    scatter_k<H1HEADS><<<cdiv(Etot * 32, 256), 256>>>(ei, E, N, bufA, p1, den1, bufB);
    bn_stats_k<<<cdiv(N, 256), 256>>>(bufB, N, bnS, bnQ);
    bn_apply_k<<<cdiv(N * DFEAT, 256), 256>>>(bufB, N, bnS, bnQ, g1, be1);

    // ---- GAT layer 2 ----
    {
        dim3 grid(DFEAT / BN, cdiv(N, BM));
        sgemm_k<<<grid, 256>>>(bufB, W2, bufA, N, DFEAT, DFEAT);
    }
    al2_k<<<cdiv(N * 32, 256), 256>>>(bufA, a2s, a2d, als2, ald2, N);
    att_denom_k<1><<<cdiv(Etot, 256), 256>>>(ei, E, N, als2, ald2, p2, den2);
    cudaMemsetAsync(bufB, 0, (size_t)N * DFEAT * sizeof(float));
    cudaMemsetAsync(bnS,  0, DFEAT * sizeof(float));
    cudaMemsetAsync(bnQ,  0, DFEAT * sizeof(float));
    scatter_k<1><<<cdiv(Etot * 32, 256), 256>>>(ei, E, N, bufA, p2, den2, bufB);
    bn_stats_k<<<cdiv(N, 256), 256>>>(bufB, N, bnS, bnQ);
    bn_apply_k<<<cdiv(N * DFEAT, 256), 256>>>(bufB, N, bnS, bnQ, g2, be2);
    // bufB now holds x_nodes

    // ---- pooling + heads ----
    pool_k<<<cdiv(N, 256), 256>>>(bufB, batch, N, poolS, poolC);
    heads_k<<<1, 256>>>(bufB, target, Wsh, bsh, Wnode, Wtype, btype, Wcrit, bcrit,
                        poolS, poolC, s2, out, N);
    nodescore_k<<<cdiv(N * 32, 256), 256>>>(bufB, batch, Wnode, bnode, s2, out, N);
}

// round 4
// speedup vs baseline: 1.2501x; 1.2501x over previous
#include <cuda_runtime.h>
#include <cstdint>

// Problem constants (fixed shapes for this dataset)
#define NNODES   50000
#define DFEAT    256
#define H1HEADS  4
#define HD1      64
#define NGRAPHS  8
#define EMAX     400000
#define ETOTMAX  (EMAX + NNODES)

// ---------------- scratch (static device globals; no allocation) ----------------
__device__ float g_bufA[NNODES * DFEAT];   // linear-layer output (h1 / h2)
__device__ float g_bufB[NNODES * DFEAT];   // aggregation output / BN in-place
__device__ float g_als1[NNODES * H1HEADS];
__device__ float g_ald1[NNODES * H1HEADS];
__device__ float g_als2[NNODES];
__device__ float g_ald2[NNODES];
__device__ int   g_cnt[NNODES + 1];        // histogram
__device__ int   g_rowst[NNODES + 1];      // exclusive offsets (N+1)
__device__ int   g_cursor[NNODES];         // working cursor for permute
__device__ int   g_src_sorted[ETOTMAX];    // src ids grouped by dst
__device__ float g_bn_sum[DFEAT];
__device__ float g_bn_sumsq[DFEAT];
__device__ float g_pool_sum[NGRAPHS * DFEAT];
__device__ float g_pool_cnt[NGRAPHS];
__device__ float g_s2[NGRAPHS];

static inline int cdiv(int a, int b) { return (a + b - 1) / b; }

// ---------------- SGEMM: C[M,Nn] = A[M,K] @ B[K,Nn], row-major fp32 ----------------
#define BM 128
#define BN 64
#define BK 16
__global__ __launch_bounds__(256) void sgemm_k(const float* __restrict__ A,
                                               const float* __restrict__ B,
                                               float* __restrict__ C,
                                               int M, int K, int Nn) {
    __shared__ float As[BK][BM + 4];
    __shared__ float Bs[BK][BN];
    int t  = threadIdx.x;
    int m0 = blockIdx.y * BM;
    int n0 = blockIdx.x * BN;
    int tx = t & 15;   // column group (x4)
    int ty = t >> 4;   // row group (x8)
    float acc[8][4];
#pragma unroll
    for (int i = 0; i < 8; i++)
#pragma unroll
        for (int j = 0; j < 4; j++) acc[i][j] = 0.f;

    for (int k0 = 0; k0 < K; k0 += BK) {
#pragma unroll
        for (int i = 0; i < 2; i++) {
            int f  = t + i * 256;
            int r  = f >> 2;
            int c4 = (f & 3) * 4;
            int gm = m0 + r;
            float4 v = make_float4(0.f, 0.f, 0.f, 0.f);
            if (gm < M) v = *(const float4*)(A + (size_t)gm * K + k0 + c4);
            As[c4 + 0][r] = v.x; As[c4 + 1][r] = v.y;
            As[c4 + 2][r] = v.z; As[c4 + 3][r] = v.w;
        }
        {
            int r  = t >> 4;
            int c4 = (t & 15) * 4;
            float4 v = *(const float4*)(B + (size_t)(k0 + r) * Nn + n0 + c4);
            *(float4*)&Bs[r][c4] = v;
        }
        __syncthreads();
#pragma unroll
        for (int k = 0; k < BK; k++) {
            float a_[8];
#pragma unroll
            for (int i = 0; i < 8; i++) a_[i] = As[k][ty * 8 + i];
            float4 b4 = *(float4*)&Bs[k][tx * 4];
            float b_[4] = {b4.x, b4.y, b4.z, b4.w};
#pragma unroll
            for (int i = 0; i < 8; i++)
#pragma unroll
                for (int j = 0; j < 4; j++) acc[i][j] += a_[i] * b_[j];
        }
        __syncthreads();
    }
#pragma unroll
    for (int i = 0; i < 8; i++) {
        int gm = m0 + ty * 8 + i;
        if (gm < M) {
            float4 v = make_float4(acc[i][0], acc[i][1], acc[i][2], acc[i][3]);
            *(float4*)(C + (size_t)gm * Nn + n0 + tx * 4) = v;
        }
    }
}

// ---------------- edge bucketing by dst (counting sort; built once, reused) ------
__global__ void hist_k(const int* __restrict__ ei, int E, int N, int* __restrict__ cnt) {
    int e = blockIdx.x * 256 + threadIdx.x;
    if (e >= E + N) return;
    int d = (e < E) ? ei[E + e] : (e - E);
    atomicAdd(&cnt[d], 1);
}

#define SCAN_T 1024
__global__ __launch_bounds__(SCAN_T) void scan_k(const int* __restrict__ cnt,
                                                 int* __restrict__ rowst, int N, int Etot) {
    __shared__ int part[SCAN_T];
    int t = threadIdx.x;
    int ch = (N + SCAN_T - 1) / SCAN_T;
    int s = 0;
    for (int k = 0; k < ch; k++) {
        int idx = t * ch + k;
        if (idx < N) s += cnt[idx];
    }
    part[t] = s;
    __syncthreads();
    for (int off = 1; off < SCAN_T; off <<= 1) {
        int v = (t >= off) ? part[t - off] : 0;
        __syncthreads();
        part[t] += v;
        __syncthreads();
    }
    int run = (t > 0) ? part[t - 1] : 0;
    for (int k = 0; k < ch; k++) {
        int idx = t * ch + k;
        if (idx < N) { rowst[idx] = run; run += cnt[idx]; }
    }
    if (t == SCAN_T - 1) rowst[N] = Etot;
}

__global__ void permute_k(const int* __restrict__ ei, int E, int N,
                          int* __restrict__ cursor, int* __restrict__ src_sorted) {
    int e = blockIdx.x * 256 + threadIdx.x;
    if (e >= E + N) return;
    int s, d;
    if (e < E) { s = ei[e]; d = ei[E + e]; } else { s = d = e - E; }
    int pos = atomicAdd(&cursor[d], 1);
    src_sorted[pos] = s;
}

// ---------------- attention logits per node (warp per node, coalesced) ----------------
__global__ void al1_k(const float* __restrict__ h, const float* __restrict__ a_src,
                      const float* __restrict__ a_dst, float* als, float* ald, int N) {
    int w    = (blockIdx.x * blockDim.x + threadIdx.x) >> 5;
    int lane = threadIdx.x & 31;
    if (w >= N) return;
    int c0 = lane * 8;
    const float* row = h + (size_t)w * DFEAT + c0;
    float s = 0.f, d = 0.f;
#pragma unroll
    for (int k = 0; k < 8; k++) {
        float v = row[k];
        s += v * a_src[c0 + k];
        d += v * a_dst[c0 + k];
    }
    // reduce within each 8-lane head group
#pragma unroll
    for (int o = 4; o; o >>= 1) {
        s += __shfl_down_sync(0xffffffffu, s, o, 8);
        d += __shfl_down_sync(0xffffffffu, d, o, 8);
    }
    if ((lane & 7) == 0) {
        int head = lane >> 3;
        als[w * H1HEADS + head] = s;
        ald[w * H1HEADS + head] = d;
    }
}

__global__ void al2_k(const float* __restrict__ h, const float* __restrict__ a_src,
                      const float* __restrict__ a_dst, float* als, float* ald, int N) {
    int w    = (blockIdx.x * blockDim.x + threadIdx.x) >> 5;
    int lane = threadIdx.x & 31;
    if (w >= N) return;
    const float* row = h + (size_t)w * DFEAT;
    float s = 0.f, d = 0.f;
#pragma unroll
    for (int j = 0; j < 8; j++) {
        int c = lane + j * 32;
        float v = row[c];
        s += v * a_src[c]; d += v * a_dst[c];
    }
#pragma unroll
    for (int o = 16; o; o >>= 1) {
        s += __shfl_down_sync(0xffffffffu, s, o);
        d += __shfl_down_sync(0xffffffffu, d, o);
    }
    if (!lane) { als[w] = s; ald[w] = d; }
}

__device__ __forceinline__ float lrelu(float v) { return v > 0.f ? v : 0.2f * v; }

// ---------------- fused GAT aggregation, warp per dst node, H=4 ----------------
__global__ __launch_bounds__(256) void gat_agg1_k(
        const int* __restrict__ rowst, const int* __restrict__ src_sorted,
        const float* __restrict__ h, const float* __restrict__ als,
        const float* __restrict__ ald, float* __restrict__ out, int N) {
    int w    = (blockIdx.x * blockDim.x + threadIdx.x) >> 5;
    int lane = threadIdx.x & 31;
    if (w >= N) return;
    int start = rowst[w], end = rowst[w + 1];
    float4 aldv = *(const float4*)&ald[w * 4];
    int c0   = lane * 8;
    int head = lane >> 3;
    float den0 = 0.f, den1 = 0.f, den2 = 0.f, den3 = 0.f;
    float acc[8];
#pragma unroll
    for (int k = 0; k < 8; k++) acc[k] = 0.f;

    for (int base = start; base < end; base += 32) {
        int e = base + lane;
        int s = 0;
        float4 pe = make_float4(0.f, 0.f, 0.f, 0.f);
        if (e < end) {
            s = src_sorted[e];
            float4 av = *(const float4*)&als[s * 4];
            pe.x = __expf(lrelu(av.x + aldv.x));
            pe.y = __expf(lrelu(av.y + aldv.y));
            pe.z = __expf(lrelu(av.z + aldv.z));
            pe.w = __expf(lrelu(av.w + aldv.w));
            den0 += pe.x; den1 += pe.y; den2 += pe.z; den3 += pe.w;
        }
        int cnt = min(32, end - base);
        for (int j = 0; j < cnt; j++) {
            int   sj = __shfl_sync(0xffffffffu, s, j);
            float px = __shfl_sync(0xffffffffu, pe.x, j);
            float py = __shfl_sync(0xffffffffu, pe.y, j);
            float pz = __shfl_sync(0xffffffffu, pe.z, j);
            float pw = __shfl_sync(0xffffffffu, pe.w, j);
            float pej = (head < 2) ? (head == 0 ? px : py) : (head == 2 ? pz : pw);
            const float4* hp = (const float4*)(h + (size_t)sj * DFEAT + c0);
            float4 v0 = hp[0], v1 = hp[1];
            acc[0] += v0.x * pej; acc[1] += v0.y * pej;
            acc[2] += v0.z * pej; acc[3] += v0.w * pej;
            acc[4] += v1.x * pej; acc[5] += v1.y * pej;
            acc[6] += v1.z * pej; acc[7] += v1.w * pej;
        }
    }
    // full-warp reduce of the 4 denominators (xor tree -> all lanes hold sums)
#pragma unroll
    for (int o = 16; o; o >>= 1) {
        den0 += __shfl_xor_sync(0xffffffffu, den0, o);
        den1 += __shfl_xor_sync(0xffffffffu, den1, o);
        den2 += __shfl_xor_sync(0xffffffffu, den2, o);
        den3 += __shfl_xor_sync(0xffffffffu, den3, o);
    }
    float den = (head < 2) ? (head == 0 ? den0 : den1) : (head == 2 ? den2 : den3);
    float inv = 1.f / (den + 1e-16f);
    float* ob = out + (size_t)w * DFEAT + c0;
    float4 o0 = make_float4(acc[0] * inv, acc[1] * inv, acc[2] * inv, acc[3] * inv);
    float4 o1 = make_float4(acc[4] * inv, acc[5] * inv, acc[6] * inv, acc[7] * inv);
    *(float4*)ob       = o0;
    *(float4*)(ob + 4) = o1;
}

// ---------------- fused GAT aggregation, warp per dst node, H=1 ----------------
__global__ __launch_bounds__(256) void gat_agg2_k(
        const int* __restrict__ rowst, const int* __restrict__ src_sorted,
        const float* __restrict__ h, const float* __restrict__ als,
        const float* __restrict__ ald, float* __restrict__ out, int N) {
    int w    = (blockIdx.x * blockDim.x + threadIdx.x) >> 5;
    int lane = threadIdx.x & 31;
    if (w >= N) return;
    int start = rowst[w], end = rowst[w + 1];
    float aldd = ald[w];
    int c0 = lane * 8;
    float den = 0.f;
    float acc[8];
#pragma unroll
    for (int k = 0; k < 8; k++) acc[k] = 0.f;

    for (int base = start; base < end; base += 32) {
        int e = base + lane;
        int s = 0;
        float pe = 0.f;
        if (e < end) {
            s = src_sorted[e];
            pe = __expf(lrelu(als[s] + aldd));
            den += pe;
        }
        int cnt = min(32, end - base);
        for (int j = 0; j < cnt; j++) {
            int   sj  = __shfl_sync(0xffffffffu, s, j);
            float pej = __shfl_sync(0xffffffffu, pe, j);
            const float4* hp = (const float4*)(h + (size_t)sj * DFEAT + c0);
            float4 v0 = hp[0], v1 = hp[1];
            acc[0] += v0.x * pej; acc[1] += v0.y * pej;
            acc[2] += v0.z * pej; acc[3] += v0.w * pej;
            acc[4] += v1.x * pej; acc[5] += v1.y * pej;
            acc[6] += v1.z * pej; acc[7] += v1.w * pej;
        }
    }
#pragma unroll
    for (int o = 16; o; o >>= 1) den += __shfl_xor_sync(0xffffffffu, den, o);
    float inv = 1.f / (den + 1e-16f);
    float* ob = out + (size_t)w * DFEAT + c0;
    float4 o0 = make_float4(acc[0] * inv, acc[1] * inv, acc[2] * inv, acc[3] * inv);
    float4 o1 = make_float4(acc[4] * inv, acc[5] * inv, acc[6] * inv, acc[7] * inv);
    *(float4*)ob       = o0;
    *(float4*)(ob + 4) = o1;
}

// ---------------- BatchNorm (training mode, biased var) ----------------
__global__ void bn_stats_k(const float* __restrict__ x, int N, float* sum, float* sumsq) {
    int c  = threadIdx.x;            // 256 = channel
    int n0 = blockIdx.x * 256;
    int n1 = min(n0 + 256, N);
    float s = 0.f, q = 0.f;
    for (int n = n0; n < n1; n++) {
        float v = x[(size_t)n * DFEAT + c];
        s += v; q += v * v;
    }
    atomicAdd(&sum[c], s);
    atomicAdd(&sumsq[c], q);
}

__global__ void bn_apply_k(float* __restrict__ x, int N,
                           const float* __restrict__ sum, const float* __restrict__ sumsq,
                           const float* __restrict__ g, const float* __restrict__ be) {
    int i = blockIdx.x * 256 + threadIdx.x;
    if (i >= N * DFEAT) return;
    int c = i & 255;
    float invN = 1.f / (float)N;
    float m = sum[c] * invN;
    float v = sumsq[c] * invN - m * m;
    float y = (x[i] - m) * rsqrtf(v + 1e-5f) * g[c] + be[c];
    x[i] = fmaxf(y, 0.f);
}

// ---------------- global mean pool (batch_index sorted) ----------------
__global__ void pool_k(const float* __restrict__ x, const int* __restrict__ batch,
                       int N, float* sums, float* cnt) {
    int c  = threadIdx.x;  // 256
    int n0 = blockIdx.x * 256;
    if (n0 >= N) return;
    int n1  = min(n0 + 256, N);
    int cur = batch[n0];
    float acc = 0.f, cacc = 0.f;
    for (int n = n0; n < n1; n++) {
        int gq = batch[n];
        if (gq != cur) {
            atomicAdd(&sums[cur * DFEAT + c], acc); acc = 0.f;
            if (c == 0) { atomicAdd(&cnt[cur], cacc); cacc = 0.f; }
            cur = gq;
        }
        acc  += x[(size_t)n * DFEAT + c];
        cacc += 1.f;
    }
    atomicAdd(&sums[cur * DFEAT + c], acc);
    if (c == 0) atomicAdd(&cnt[cur], cacc);
}

// ---------------- small heads ----------------
__global__ void heads_k(const float* __restrict__ xn, const int* __restrict__ target,
                        const float* __restrict__ Wsh, const float* __restrict__ bsh,
                        const float* __restrict__ Wnode,
                        const float* __restrict__ Wtype, const float* __restrict__ btype,
                        const float* __restrict__ Wcrit, const float* __restrict__ bcrit,
                        const float* __restrict__ pool_sums, const float* __restrict__ pool_cnt,
                        float* __restrict__ s2, float* __restrict__ out, int N) {
    __shared__ float gf[NGRAPHS][DFEAT];
    __shared__ float sh[NGRAPHS][DFEAT];
    int t = threadIdx.x;  // 256
    for (int b = 0; b < NGRAPHS; b++)
        gf[b][t] = pool_sums[b * DFEAT + t] / fmaxf(pool_cnt[b], 1.f);
    __syncthreads();
    for (int b = 0; b < NGRAPHS; b++) {
        float acc = bsh[t];
        for (int k = 0; k < DFEAT; k++) acc += gf[b][k] * Wsh[k * DFEAT + t];
        sh[b][t] = fmaxf(acc, 0.f);
    }
    __syncthreads();
    {
        int wq = t >> 5, lane = t & 31;
        float a = 0.f;
#pragma unroll
        for (int j = 0; j < 8; j++) { int c = lane + j * 32; a += sh[wq][c] * Wnode[256 + c]; }
#pragma unroll
        for (int o = 16; o; o >>= 1) a += __shfl_down_sync(0xffffffffu, a, o);
        if (!lane) s2[wq] = a;
    }
    if (t < 32) {
        int b = t >> 2, aa = t & 3;
        int tn = target[b];
        float acc = btype[aa];
        for (int c = 0; c < DFEAT; c++) acc += sh[b][c] * Wtype[c * 4 + aa];
        for (int c = 0; c < DFEAT; c++) acc += xn[(size_t)tn * DFEAT + c] * Wtype[(256 + c) * 4 + aa];
        out[N + t] = acc;
    }
    if (t >= 64 && t < 64 + NGRAPHS) {
        int b = t - 64;
        float acc = bcrit[0];
        for (int c = 0; c < DFEAT; c++) acc += sh[b][c] * Wcrit[c];
        out[N + 32 + b] = acc;
    }
}

// ---------------- node scores: warp per node ----------------
__global__ void nodescore_k(const float* __restrict__ xn, const int* __restrict__ batch,
                            const float* __restrict__ Wnode, const float* __restrict__ bnode,
                            const float* __restrict__ s2, float* __restrict__ out, int N) {
    int w    = (blockIdx.x * blockDim.x + threadIdx.x) >> 5;
    int lane = threadIdx.x & 31;
    if (w >= N) return;
    const float* row = xn + (size_t)w * DFEAT;
    float a = 0.f;
#pragma unroll
    for (int j = 0; j < 8; j++) { int c = lane + j * 32; a += row[c] * Wnode[c]; }
#pragma unroll
    for (int o = 16; o; o >>= 1) a += __shfl_down_sync(0xffffffffu, a, o);
    if (!lane) out[w] = a + s2[batch[w]] + bnode[0];
}

// ---------------- host orchestration ----------------
extern "C" void kernel_launch(void* const* d_in, const int* in_sizes, int n_in,
                              void* d_out, int out_size) {
    const float* x      = (const float*)d_in[0];
    const int*   ei     = (const int*)d_in[1];
    const int*   batch  = (const int*)d_in[2];
    const int*   target = (const int*)d_in[3];
    const float* W1     = (const float*)d_in[4];
    const float* a1s    = (const float*)d_in[5];
    const float* a1d    = (const float*)d_in[6];
    const float* W2     = (const float*)d_in[8];
    const float* a2s    = (const float*)d_in[9];
    const float* a2d    = (const float*)d_in[10];
    const float* g1     = (const float*)d_in[12];
    const float* be1    = (const float*)d_in[13];
    const float* g2     = (const float*)d_in[14];
    const float* be2    = (const float*)d_in[15];
    const float* Wsh    = (const float*)d_in[16];
    const float* bsh    = (const float*)d_in[17];
    const float* Wnode  = (const float*)d_in[18];
    const float* bnode  = (const float*)d_in[19];
    const float* Wtype  = (const float*)d_in[20];
    const float* btype  = (const float*)d_in[21];
    const float* Wcrit  = (const float*)d_in[22];
    const float* bcrit  = (const float*)d_in[23];
    float* out = (float*)d_out;

    int N = in_sizes[2];
    int F = in_sizes[0] / N;
    int E = in_sizes[1] / 2;
    int Etot = E + N;

    float *bufA, *bufB, *als1, *ald1, *als2, *ald2;
    float *bnS, *bnQ, *poolS, *poolC, *s2;
    int *cnt, *rowst, *cursor, *src_sorted;
    cudaGetSymbolAddress((void**)&bufA,  g_bufA);
    cudaGetSymbolAddress((void**)&bufB,  g_bufB);
    cudaGetSymbolAddress((void**)&als1,  g_als1);
    cudaGetSymbolAddress((void**)&ald1,  g_ald1);
    cudaGetSymbolAddress((void**)&als2,  g_als2);
    cudaGetSymbolAddress((void**)&ald2,  g_ald2);
    cudaGetSymbolAddress((void**)&cnt,   g_cnt);
    cudaGetSymbolAddress((void**)&rowst, g_rowst);
    cudaGetSymbolAddress((void**)&cursor, g_cursor);
    cudaGetSymbolAddress((void**)&src_sorted, g_src_sorted);
    cudaGetSymbolAddress((void**)&bnS,   g_bn_sum);
    cudaGetSymbolAddress((void**)&bnQ,   g_bn_sumsq);
    cudaGetSymbolAddress((void**)&poolS, g_pool_sum);
    cudaGetSymbolAddress((void**)&poolC, g_pool_cnt);
    cudaGetSymbolAddress((void**)&s2,    g_s2);

    // ---- zero init (async memsets; graph-capturable) ----
    cudaMemsetAsync(cnt,   0, (size_t)(N + 1) * sizeof(int));
    cudaMemsetAsync(poolS, 0, NGRAPHS * DFEAT * sizeof(float));
    cudaMemsetAsync(poolC, 0, NGRAPHS * sizeof(float));
    cudaMemsetAsync(bnS,   0, DFEAT * sizeof(float));
    cudaMemsetAsync(bnQ,   0, DFEAT * sizeof(float));

    // ---- edge bucketing (shared by both layers) ----
    hist_k<<<cdiv(Etot, 256), 256>>>(ei, E, N, cnt);
    scan_k<<<1, SCAN_T>>>(cnt, rowst, N, Etot);
    cudaMemcpyAsync(cursor, rowst, (size_t)N * sizeof(int), cudaMemcpyDeviceToDevice);
    permute_k<<<cdiv(Etot, 256), 256>>>(ei, E, N, cursor, src_sorted);

    // ---- GAT layer 1 ----
    {
        dim3 grid(DFEAT / BN, cdiv(N, BM));
        sgemm_k<<<grid, 256>>>(x, W1, bufA, N, F, DFEAT);
    }
    al1_k<<<cdiv(N * 32, 256), 256>>>(bufA, a1s, a1d, als1, ald1, N);
    gat_agg1_k<<<cdiv(N * 32, 256), 256>>>(rowst, src_sorted, bufA, als1, ald1, bufB, N);
    bn_stats_k<<<cdiv(N, 256), 256>>>(bufB, N, bnS, bnQ);
    bn_apply_k<<<cdiv(N * DFEAT, 256), 256>>>(bufB, N, bnS, bnQ, g1, be1);

    // ---- GAT layer 2 ----
    {
        dim3 grid(DFEAT / BN, cdiv(N, BM));
        sgemm_k<<<grid, 256>>>(bufB, W2, bufA, N, DFEAT, DFEAT);
    }
    al2_k<<<cdiv(N * 32, 256), 256>>>(bufA, a2s, a2d, als2, ald2, N);
    gat_agg2_k<<<cdiv(N * 32, 256), 256>>>(rowst, src_sorted, bufA, als2, ald2, bufB, N);
    cudaMemsetAsync(bnS, 0, DFEAT * sizeof(float));
    cudaMemsetAsync(bnQ, 0, DFEAT * sizeof(float));
    bn_stats_k<<<cdiv(N, 256), 256>>>(bufB, N, bnS, bnQ);
    bn_apply_k<<<cdiv(N * DFEAT, 256), 256>>>(bufB, N, bnS, bnQ, g2, be2);
    // bufB now holds x_nodes

    // ---- pooling + heads ----
    pool_k<<<cdiv(N, 256), 256>>>(bufB, batch, N, poolS, poolC);
    heads_k<<<1, 256>>>(bufB, target, Wsh, bsh, Wnode, Wtype, btype, Wcrit, bcrit,
                        poolS, poolC, s2, out, N);
    nodescore_k<<<cdiv(N * 32, 256), 256>>>(bufB, batch, Wnode, bnode, s2, out, N);
}

// round 5
// speedup vs baseline: 1.4915x; 1.1931x over previous
#include <cuda_runtime.h>
#include <cstdint>

// Problem constants (fixed shapes for this dataset)
#define NNODES   50000
#define DFEAT    256
#define H1HEADS  4
#define NGRAPHS  8
#define EMAX     400000
#define ETOTMAX  (EMAX + NNODES)

// ---------------- scratch (static device globals; no allocation) ----------------
__device__ float g_bufA[NNODES * DFEAT];   // linear-layer output (h1 / h2)
__device__ float g_bufB[NNODES * DFEAT];   // aggregation output
__device__ float g_als1[NNODES * H1HEADS];
__device__ float g_ald1[NNODES * H1HEADS];
__device__ float g_als2[NNODES];
__device__ float g_ald2[NNODES];
__device__ int   g_cnt[NNODES + 1];
__device__ int   g_rowst[NNODES + 1];
__device__ int   g_cursor[NNODES];
__device__ int   g_src_sorted[ETOTMAX];
__device__ float g_bn_sum[DFEAT];
__device__ float g_bn_sumsq[DFEAT];
__device__ float g_sc1[DFEAT];
__device__ float g_sh1[DFEAT];
__device__ float g_sc2[DFEAT];
__device__ float g_sh2[DFEAT];
__device__ float g_pool_sum[NGRAPHS * DFEAT];
__device__ float g_pool_cnt[NGRAPHS];
__device__ float g_s2[NGRAPHS];

static inline int cdiv(int a, int b) { return (a + b - 1) / b; }

// ---------------- SGEMM 128x128x16, 8x8/thread, fused BN-on-A + AL epilogue ------
// ALH: 0=no attention epilogue, 4=layer1 (4 heads of 64), 1=layer2 (single head)
// BNA: apply y=relu(a*sc[k]+sh[k]) per channel while loading A tile
#define TM 128
#define TN 128
#define TK 16
template <int ALH, bool BNA>
__global__ __launch_bounds__(256) void sgemm_k(
        const float* __restrict__ A, const float* __restrict__ B,
        float* __restrict__ C, int M, int K, int Nn,
        const float* __restrict__ sc, const float* __restrict__ sh,
        const float* __restrict__ asrc, const float* __restrict__ adst,
        float* __restrict__ als, float* __restrict__ ald) {
    __shared__ float As[TK][TM + 4];
    __shared__ float Bs[TK][TN];
    int t  = threadIdx.x;
    int m0 = blockIdx.y * TM;
    int n0 = blockIdx.x * TN;
    int tx = t & 15;   // 16 col groups (x8)
    int ty = t >> 4;   // 16 row groups (x8)
    float acc[8][8];
#pragma unroll
    for (int i = 0; i < 8; i++)
#pragma unroll
        for (int j = 0; j < 8; j++) acc[i][j] = 0.f;

    for (int k0 = 0; k0 < K; k0 += TK) {
        // A tile: 128 rows x 16 cols = 512 float4, 2 per thread, stored transposed
#pragma unroll
        for (int i = 0; i < 2; i++) {
            int f  = t + i * 256;
            int r  = f >> 2;
            int c4 = (f & 3) * 4;
            int gm = m0 + r;
            float4 v = make_float4(0.f, 0.f, 0.f, 0.f);
            if (gm < M) v = *(const float4*)(A + (size_t)gm * K + k0 + c4);
            if (BNA) {
                v.x = fmaxf(v.x * sc[k0 + c4 + 0] + sh[k0 + c4 + 0], 0.f);
                v.y = fmaxf(v.y * sc[k0 + c4 + 1] + sh[k0 + c4 + 1], 0.f);
                v.z = fmaxf(v.z * sc[k0 + c4 + 2] + sh[k0 + c4 + 2], 0.f);
                v.w = fmaxf(v.w * sc[k0 + c4 + 3] + sh[k0 + c4 + 3], 0.f);
            }
            As[c4 + 0][r] = v.x; As[c4 + 1][r] = v.y;
            As[c4 + 2][r] = v.z; As[c4 + 3][r] = v.w;
        }
        // B tile: 16 rows x 128 cols = 512 float4, 2 per thread
#pragma unroll
        for (int i = 0; i < 2; i++) {
            int f  = t + i * 256;
            int r  = f >> 5;
            int c4 = (f & 31) * 4;
            float4 v = *(const float4*)(B + (size_t)(k0 + r) * Nn + n0 + c4);
            *(float4*)&Bs[r][c4] = v;
        }
        __syncthreads();
#pragma unroll
        for (int k = 0; k < TK; k++) {
            float a_[8], b_[8];
            *(float4*)(a_)     = *(float4*)&As[k][ty * 8];
            *(float4*)(a_ + 4) = *(float4*)&As[k][ty * 8 + 4];
            *(float4*)(b_)     = *(float4*)&Bs[k][tx * 8];
            *(float4*)(b_ + 4) = *(float4*)&Bs[k][tx * 8 + 4];
#pragma unroll
            for (int i = 0; i < 8; i++)
#pragma unroll
                for (int j = 0; j < 8; j++) acc[i][j] += a_[i] * b_[j];
        }
        __syncthreads();
    }

    // attention-vector slices for this thread's 8 columns
    float as_r[8], ad_r[8];
    if (ALH) {
#pragma unroll
        for (int j = 0; j < 8; j++) {
            int col = n0 + tx * 8 + j;
            as_r[j] = asrc[col];
            ad_r[j] = adst[col];
        }
    }

#pragma unroll
    for (int i = 0; i < 8; i++) {
        int gm = m0 + ty * 8 + i;
        if (gm < M) {
            float* cp = C + (size_t)gm * Nn + n0 + tx * 8;
            *(float4*)cp       = make_float4(acc[i][0], acc[i][1], acc[i][2], acc[i][3]);
            *(float4*)(cp + 4) = make_float4(acc[i][4], acc[i][5], acc[i][6], acc[i][7]);
            if (ALH) {
                float s = 0.f, d = 0.f;
#pragma unroll
                for (int j = 0; j < 8; j++) { s += acc[i][j] * as_r[j]; d += acc[i][j] * ad_r[j]; }
                if (ALH == 4) {
                    // groups of 8 lanes (same ty, same 64-col head)
#pragma unroll
                    for (int o = 4; o; o >>= 1) {
                        s += __shfl_down_sync(0xffffffffu, s, o, 8);
                        d += __shfl_down_sync(0xffffffffu, d, o, 8);
                    }
                    if ((tx & 7) == 0) {
                        int head = (n0 + tx * 8) >> 6;
                        atomicAdd(&als[gm * 4 + head], s);
                        atomicAdd(&ald[gm * 4 + head], d);
                    }
                } else {
                    // groups of 16 lanes (same ty)
#pragma unroll
                    for (int o = 8; o; o >>= 1) {
                        s += __shfl_down_sync(0xffffffffu, s, o, 16);
                        d += __shfl_down_sync(0xffffffffu, d, o, 16);
                    }
                    if (tx == 0) {
                        atomicAdd(&als[gm], s);
                        atomicAdd(&ald[gm], d);
                    }
                }
            }
        }
    }
}

// ---------------- edge bucketing by dst (counting sort; built once, reused) ------
__global__ void hist_k(const int* __restrict__ ei, int E, int N, int* __restrict__ cnt) {
    int e = blockIdx.x * 256 + threadIdx.x;
    if (e >= E + N) return;
    int d = (e < E) ? ei[E + e] : (e - E);
    atomicAdd(&cnt[d], 1);
}

#define SCAN_T 1024
__global__ __launch_bounds__(SCAN_T) void scan_k(const int* __restrict__ cnt,
                                                 int* __restrict__ rowst, int N, int Etot) {
    __shared__ int part[SCAN_T];
    int t = threadIdx.x;
    int ch = (N + SCAN_T - 1) / SCAN_T;
    int s = 0;
    for (int k = 0; k < ch; k++) {
        int idx = t * ch + k;
        if (idx < N) s += cnt[idx];
    }
    part[t] = s;
    __syncthreads();
    for (int off = 1; off < SCAN_T; off <<= 1) {
        int v = (t >= off) ? part[t - off] : 0;
        __syncthreads();
        part[t] += v;
        __syncthreads();
    }
    int run = (t > 0) ? part[t - 1] : 0;
    for (int k = 0; k < ch; k++) {
        int idx = t * ch + k;
        if (idx < N) { rowst[idx] = run; run += cnt[idx]; }
    }
    if (t == SCAN_T - 1) rowst[N] = Etot;
}

__global__ void permute_k(const int* __restrict__ ei, int E, int N,
                          int* __restrict__ cursor, int* __restrict__ src_sorted) {
    int e = blockIdx.x * 256 + threadIdx.x;
    if (e >= E + N) return;
    int s, d;
    if (e < E) { s = ei[e]; d = ei[E + e]; } else { s = d = e - E; }
    int pos = atomicAdd(&cursor[d], 1);
    src_sorted[pos] = s;
}

__device__ __forceinline__ float lrelu(float v) { return v > 0.f ? v : 0.2f * v; }

// ---------------- fused GAT aggregation, warp per dst node, H=4 ----------------
__global__ __launch_bounds__(256) void gat_agg1_k(
        const int* __restrict__ rowst, const int* __restrict__ src_sorted,
        const float* __restrict__ h, const float* __restrict__ als,
        const float* __restrict__ ald, float* __restrict__ out, int N) {
    int w    = (blockIdx.x * blockDim.x + threadIdx.x) >> 5;
    int lane = threadIdx.x & 31;
    if (w >= N) return;
    int start = rowst[w], end = rowst[w + 1];
    float4 aldv = *(const float4*)&ald[w * 4];
    int c0   = lane * 8;
    int head = lane >> 3;
    float den0 = 0.f, den1 = 0.f, den2 = 0.f, den3 = 0.f;
    float acc[8];
#pragma unroll
    for (int k = 0; k < 8; k++) acc[k] = 0.f;

    for (int base = start; base < end; base += 32) {
        int e = base + lane;
        int s = 0;
        float4 pe = make_float4(0.f, 0.f, 0.f, 0.f);
        if (e < end) {
            s = src_sorted[e];
            float4 av = *(const float4*)&als[s * 4];
            pe.x = __expf(lrelu(av.x + aldv.x));
            pe.y = __expf(lrelu(av.y + aldv.y));
            pe.z = __expf(lrelu(av.z + aldv.z));
            pe.w = __expf(lrelu(av.w + aldv.w));
            den0 += pe.x; den1 += pe.y; den2 += pe.z; den3 += pe.w;
        }
        int cnt = min(32, end - base);
        for (int j = 0; j < cnt; j++) {
            int   sj = __shfl_sync(0xffffffffu, s, j);
            float px = __shfl_sync(0xffffffffu, pe.x, j);
            float py = __shfl_sync(0xffffffffu, pe.y, j);
            float pz = __shfl_sync(0xffffffffu, pe.z, j);
            float pw = __shfl_sync(0xffffffffu, pe.w, j);
            float pej = (head < 2) ? (head == 0 ? px : py) : (head == 2 ? pz : pw);
            const float4* hp = (const float4*)(h + (size_t)sj * DFEAT + c0);
            float4 v0 = hp[0], v1 = hp[1];
            acc[0] += v0.x * pej; acc[1] += v0.y * pej;
            acc[2] += v0.z * pej; acc[3] += v0.w * pej;
            acc[4] += v1.x * pej; acc[5] += v1.y * pej;
            acc[6] += v1.z * pej; acc[7] += v1.w * pej;
        }
    }
#pragma unroll
    for (int o = 16; o; o >>= 1) {
        den0 += __shfl_xor_sync(0xffffffffu, den0, o);
        den1 += __shfl_xor_sync(0xffffffffu, den1, o);
        den2 += __shfl_xor_sync(0xffffffffu, den2, o);
        den3 += __shfl_xor_sync(0xffffffffu, den3, o);
    }
    float den = (head < 2) ? (head == 0 ? den0 : den1) : (head == 2 ? den2 : den3);
    float inv = 1.f / (den + 1e-16f);
    float* ob = out + (size_t)w * DFEAT + c0;
    *(float4*)ob       = make_float4(acc[0] * inv, acc[1] * inv, acc[2] * inv, acc[3] * inv);
    *(float4*)(ob + 4) = make_float4(acc[4] * inv, acc[5] * inv, acc[6] * inv, acc[7] * inv);
}

// ---------------- fused GAT aggregation, warp per dst node, H=1 ----------------
__global__ __launch_bounds__(256) void gat_agg2_k(
        const int* __restrict__ rowst, const int* __restrict__ src_sorted,
        const float* __restrict__ h, const float* __restrict__ als,
        const float* __restrict__ ald, float* __restrict__ out, int N) {
    int w    = (blockIdx.x * blockDim.x + threadIdx.x) >> 5;
    int lane = threadIdx.x & 31;
    if (w >= N) return;
    int start = rowst[w], end = rowst[w + 1];
    float aldd = ald[w];
    int c0 = lane * 8;
    float den = 0.f;
    float acc[8];
#pragma unroll
    for (int k = 0; k < 8; k++) acc[k] = 0.f;

    for (int base = start; base < end; base += 32) {
        int e = base + lane;
        int s = 0;
        float pe = 0.f;
        if (e < end) {
            s = src_sorted[e];
            pe = __expf(lrelu(als[s] + aldd));
            den += pe;
        }
        int cnt = min(32, end - base);
        for (int j = 0; j < cnt; j++) {
            int   sj  = __shfl_sync(0xffffffffu, s, j);
            float pej = __shfl_sync(0xffffffffu, pe, j);
            const float4* hp = (const float4*)(h + (size_t)sj * DFEAT + c0);
            float4 v0 = hp[0], v1 = hp[1];
            acc[0] += v0.x * pej; acc[1] += v0.y * pej;
            acc[2] += v0.z * pej; acc[3] += v0.w * pej;
            acc[4] += v1.x * pej; acc[5] += v1.y * pej;
            acc[6] += v1.z * pej; acc[7] += v1.w * pej;
        }
    }
#pragma unroll
    for (int o = 16; o; o >>= 1) den += __shfl_xor_sync(0xffffffffu, den, o);
    float inv = 1.f / (den + 1e-16f);
    float* ob = out + (size_t)w * DFEAT + c0;
    *(float4*)ob       = make_float4(acc[0] * inv, acc[1] * inv, acc[2] * inv, acc[3] * inv);
    *(float4*)(ob + 4) = make_float4(acc[4] * inv, acc[5] * inv, acc[6] * inv, acc[7] * inv);
}

// ---------------- BatchNorm stats + coefficient prep ----------------
__global__ void bn_stats_k(const float* __restrict__ x, int N, float* sum, float* sumsq) {
    int c  = threadIdx.x;            // 256 = channel
    int n0 = blockIdx.x * 256;
    int n1 = min(n0 + 256, N);
    float s = 0.f, q = 0.f;
    for (int n = n0; n < n1; n++) {
        float v = x[(size_t)n * DFEAT + c];
        s += v; q += v * v;
    }
    atomicAdd(&sum[c], s);
    atomicAdd(&sumsq[c], q);
}

__global__ void bnprep_k(const float* __restrict__ sum, const float* __restrict__ sumsq,
                         const float* __restrict__ g, const float* __restrict__ be,
                         float* __restrict__ sc, float* __restrict__ sh, int N) {
    int c = threadIdx.x;
    float invN = 1.f / (float)N;
    float m = sum[c] * invN;
    float v = sumsq[c] * invN - m * m;
    float s = g[c] * rsqrtf(v + 1e-5f);
    sc[c] = s;
    sh[c] = be[c] - m * s;
}

// ---------------- fused BN2-apply + relu + nodescore dot (block per node) --------
__global__ __launch_bounds__(256) void bn2_node_k(
        float* __restrict__ x, const float* __restrict__ sc, const float* __restrict__ sh,
        const float* __restrict__ Wnode, float* __restrict__ out, int N) {
    __shared__ float red[8];
    int n = blockIdx.x;
    int c = threadIdx.x;
    float y = fmaxf(x[(size_t)n * DFEAT + c] * sc[c] + sh[c], 0.f);
    x[(size_t)n * DFEAT + c] = y;
    float dot = y * Wnode[c];
#pragma unroll
    for (int o = 16; o; o >>= 1) dot += __shfl_down_sync(0xffffffffu, dot, o);
    if ((c & 31) == 0) red[c >> 5] = dot;
    __syncthreads();
    if (c == 0) {
        float s = 0.f;
#pragma unroll
        for (int i = 0; i < 8; i++) s += red[i];
        out[n] = s;   // raw dot; s2 + bias added by fixup_k
    }
}

// ---------------- global mean pool (batch_index sorted) ----------------
__global__ void pool_k(const float* __restrict__ x, const int* __restrict__ batch,
                       int N, float* sums, float* cnt) {
    int c  = threadIdx.x;  // 256
    int n0 = blockIdx.x * 256;
    if (n0 >= N) return;
    int n1  = min(n0 + 256, N);
    int cur = batch[n0];
    float acc = 0.f, cacc = 0.f;
    for (int n = n0; n < n1; n++) {
        int gq = batch[n];
        if (gq != cur) {
            atomicAdd(&sums[cur * DFEAT + c], acc); acc = 0.f;
            if (c == 0) { atomicAdd(&cnt[cur], cacc); cacc = 0.f; }
            cur = gq;
        }
        acc  += x[(size_t)n * DFEAT + c];
        cacc += 1.f;
    }
    atomicAdd(&sums[cur * DFEAT + c], acc);
    if (c == 0) atomicAdd(&cnt[cur], cacc);
}

// ---------------- heads: block per graph ----------------
__global__ __launch_bounds__(256) void heads_k(
        const float* __restrict__ xn, const int* __restrict__ target,
        const float* __restrict__ Wsh, const float* __restrict__ bsh,
        const float* __restrict__ Wnode,
        const float* __restrict__ Wtype, const float* __restrict__ btype,
        const float* __restrict__ Wcrit, const float* __restrict__ bcrit,
        const float* __restrict__ pool_sums, const float* __restrict__ pool_cnt,
        float* __restrict__ s2, float* __restrict__ out, int N) {
    __shared__ float gf[DFEAT];
    __shared__ float sh[DFEAT];
    __shared__ float part[8][6];
    int b = blockIdx.x;
    int t = threadIdx.x;
    gf[t] = pool_sums[b * DFEAT + t] / fmaxf(pool_cnt[b], 1.f);
    __syncthreads();
    float acc = bsh[t];
    for (int k = 0; k < DFEAT; k++) acc += gf[k] * Wsh[k * DFEAT + t];
    sh[t] = fmaxf(acc, 0.f);
    __syncthreads();

    int tn = target[b];
    float xv = xn[(size_t)tn * DFEAT + t];
    float v[6];
    v[0] = sh[t] * Wnode[256 + t];
    v[1] = sh[t] * Wcrit[t];
#pragma unroll
    for (int a = 0; a < 4; a++)
        v[2 + a] = sh[t] * Wtype[t * 4 + a] + xv * Wtype[(256 + t) * 4 + a];
#pragma unroll
    for (int o = 16; o; o >>= 1)
#pragma unroll
        for (int i = 0; i < 6; i++) v[i] += __shfl_down_sync(0xffffffffu, v[i], o);
    if ((t & 31) == 0)
#pragma unroll
        for (int i = 0; i < 6; i++) part[t >> 5][i] = v[i];
    __syncthreads();
    if (t == 0) {
        float r[6] = {0.f, 0.f, 0.f, 0.f, 0.f, 0.f};
        for (int w = 0; w < 8; w++)
#pragma unroll
            for (int i = 0; i < 6; i++) r[i] += part[w][i];
        s2[b] = r[0];
        out[N + 32 + b] = r[1] + bcrit[0];
#pragma unroll
        for (int a = 0; a < 4; a++) out[N + b * 4 + a] = r[2 + a] + btype[a];
    }
}

// ---------------- fixup: add s2[batch] + bnode to node scores ----------------
__global__ void fixup_k(float* __restrict__ out, const int* __restrict__ batch,
                        const float* __restrict__ s2, const float* __restrict__ bnode, int N) {
    int i = blockIdx.x * 256 + threadIdx.x;
    if (i < N) out[i] += s2[batch[i]] + bnode[0];
}

// ---------------- host orchestration ----------------
extern "C" void kernel_launch(void* const* d_in, const int* in_sizes, int n_in,
                              void* d_out, int out_size) {
    const float* x      = (const float*)d_in[0];
    const int*   ei     = (const int*)d_in[1];
    const int*   batch  = (const int*)d_in[2];
    const int*   target = (const int*)d_in[3];
    const float* W1     = (const float*)d_in[4];
    const float* a1s    = (const float*)d_in[5];
    const float* a1d    = (const float*)d_in[6];
    const float* W2     = (const float*)d_in[8];
    const float* a2s    = (const float*)d_in[9];
    const float* a2d    = (const float*)d_in[10];
    const float* g1     = (const float*)d_in[12];
    const float* be1    = (const float*)d_in[13];
    const float* g2     = (const float*)d_in[14];
    const float* be2    = (const float*)d_in[15];
    const float* Wsh    = (const float*)d_in[16];
    const float* bsh    = (const float*)d_in[17];
    const float* Wnode  = (const float*)d_in[18];
    const float* bnode  = (const float*)d_in[19];
    const float* Wtype  = (const float*)d_in[20];
    const float* btype  = (const float*)d_in[21];
    const float* Wcrit  = (const float*)d_in[22];
    const float* bcrit  = (const float*)d_in[23];
    float* out = (float*)d_out;

    int N = in_sizes[2];
    int F = in_sizes[0] / N;
    int E = in_sizes[1] / 2;
    int Etot = E + N;

    float *bufA, *bufB, *als1, *ald1, *als2, *ald2;
    float *bnS, *bnQ, *sc1, *sh1, *sc2, *sh2, *poolS, *poolC, *s2;
    int *cnt, *rowst, *cursor, *src_sorted;
    cudaGetSymbolAddress((void**)&bufA,  g_bufA);
    cudaGetSymbolAddress((void**)&bufB,  g_bufB);
    cudaGetSymbolAddress((void**)&als1,  g_als1);
    cudaGetSymbolAddress((void**)&ald1,  g_ald1);
    cudaGetSymbolAddress((void**)&als2,  g_als2);
    cudaGetSymbolAddress((void**)&ald2,  g_ald2);
    cudaGetSymbolAddress((void**)&cnt,   g_cnt);
    cudaGetSymbolAddress((void**)&rowst, g_rowst);
    cudaGetSymbolAddress((void**)&cursor, g_cursor);
    cudaGetSymbolAddress((void**)&src_sorted, g_src_sorted);
    cudaGetSymbolAddress((void**)&bnS,   g_bn_sum);
    cudaGetSymbolAddress((void**)&bnQ,   g_bn_sumsq);
    cudaGetSymbolAddress((void**)&sc1,   g_sc1);
    cudaGetSymbolAddress((void**)&sh1,   g_sh1);
    cudaGetSymbolAddress((void**)&sc2,   g_sc2);
    cudaGetSymbolAddress((void**)&sh2,   g_sh2);
    cudaGetSymbolAddress((void**)&poolS, g_pool_sum);
    cudaGetSymbolAddress((void**)&poolC, g_pool_cnt);
    cudaGetSymbolAddress((void**)&s2,    g_s2);

    // ---- zero init (async memsets; graph-capturable) ----
    cudaMemsetAsync(cnt,   0, (size_t)(N + 1) * sizeof(int));
    cudaMemsetAsync(als1,  0, (size_t)N * H1HEADS * sizeof(float));
    cudaMemsetAsync(ald1,  0, (size_t)N * H1HEADS * sizeof(float));
    cudaMemsetAsync(als2,  0, (size_t)N * sizeof(float));
    cudaMemsetAsync(ald2,  0, (size_t)N * sizeof(float));
    cudaMemsetAsync(poolS, 0, NGRAPHS * DFEAT * sizeof(float));
    cudaMemsetAsync(poolC, 0, NGRAPHS * sizeof(float));
    cudaMemsetAsync(bnS,   0, DFEAT * sizeof(float));
    cudaMemsetAsync(bnQ,   0, DFEAT * sizeof(float));

    // ---- edge bucketing (shared by both layers) ----
    hist_k<<<cdiv(Etot, 256), 256>>>(ei, E, N, cnt);
    scan_k<<<1, SCAN_T>>>(cnt, rowst, N, Etot);
    cudaMemcpyAsync(cursor, rowst, (size_t)N * sizeof(int), cudaMemcpyDeviceToDevice);
    permute_k<<<cdiv(Etot, 256), 256>>>(ei, E, N, cursor, src_sorted);

    dim3 ggrid(DFEAT / TN, cdiv(N, TM));

    // ---- GAT layer 1: GEMM(+al1 epilogue) -> agg -> BN stats ----
    sgemm_k<4, false><<<ggrid, 256>>>(x, W1, bufA, N, F, DFEAT,
                                      nullptr, nullptr, a1s, a1d, als1, ald1);
    gat_agg1_k<<<cdiv(N * 32, 256), 256>>>(rowst, src_sorted, bufA, als1, ald1, bufB, N);
    bn_stats_k<<<cdiv(N, 256), 256>>>(bufB, N, bnS, bnQ);
    bnprep_k<<<1, 256>>>(bnS, bnQ, g1, be1, sc1, sh1, N);

    // ---- GAT layer 2: GEMM(BN1 fused on A, +al2 epilogue) -> agg -> BN stats ----
    sgemm_k<1, true><<<ggrid, 256>>>(bufB, W2, bufA, N, DFEAT, DFEAT,
                                     sc1, sh1, a2s, a2d, als2, ald2);
    gat_agg2_k<<<cdiv(N * 32, 256), 256>>>(rowst, src_sorted, bufA, als2, ald2, bufB, N);
    cudaMemsetAsync(bnS, 0, DFEAT * sizeof(float));
    cudaMemsetAsync(bnQ, 0, DFEAT * sizeof(float));
    bn_stats_k<<<cdiv(N, 256), 256>>>(bufB, N, bnS, bnQ);
    bnprep_k<<<1, 256>>>(bnS, bnQ, g2, be2, sc2, sh2, N);

    // ---- BN2 apply + nodescore dot (bufB -> x_nodes in place; raw dots -> out) --
    bn2_node_k<<<N, 256>>>(bufB, sc2, sh2, Wnode, out, N);

    // ---- pooling + heads + fixup ----
    pool_k<<<cdiv(N, 256), 256>>>(bufB, batch, N, poolS, poolC);
    heads_k<<<NGRAPHS, 256>>>(bufB, target, Wsh, bsh, Wnode, Wtype, btype, Wcrit, bcrit,
                              poolS, poolC, s2, out, N);
    fixup_k<<<cdiv(N, 256), 256>>>(out, batch, s2, bnode, N);
}

// round 6
// speedup vs baseline: 1.4943x; 1.0019x over previous
#include <cuda_runtime.h>
#include <cstdint>

// Problem constants (fixed shapes for this dataset)
#define NNODES   50000
#define DFEAT    256
#define H1HEADS  4
#define NGRAPHS  8
#define EMAX     400000
#define ETOTMAX  (EMAX + NNODES)

// ---------------- scratch (static device globals; no allocation) ----------------
__device__ float g_bufA[NNODES * DFEAT];   // linear-layer output (h1 / h2)
__device__ float g_bufB[NNODES * DFEAT];   // aggregation output
__device__ float g_als1[NNODES * H1HEADS];
__device__ float g_ald1[NNODES * H1HEADS];
__device__ float g_als2[NNODES];
__device__ float g_ald2[NNODES];
__device__ int   g_cnt[NNODES + 1];
__device__ int   g_rowst[NNODES + 1];
__device__ int   g_cursor[NNODES];
__device__ int   g_src_sorted[ETOTMAX];
__device__ float g_bn_sum[DFEAT];
__device__ float g_bn_sumsq[DFEAT];
__device__ float g_sc1[DFEAT];
__device__ float g_sh1[DFEAT];
__device__ float g_sc2[DFEAT];
__device__ float g_sh2[DFEAT];
__device__ float g_pool_sum[NGRAPHS * DFEAT];
__device__ float g_s2[NGRAPHS];

static inline int cdiv(int a, int b) { return (a + b - 1) / b; }

// ---------------- SGEMM 128 x (16*NR) x 16, 8xNR/thread -------------------------
// ALH: 0=none, 4=layer1 attention epilogue (requires NR=4), 1=layer2 (NR=8)
// BNA: apply y=relu(a*sc[k]+sh[k]) per channel while loading A tile
#define TM 128
#define TK 16
template <int NR, int ALH, bool BNA>
__global__ __launch_bounds__(256) void sgemm_k(
        const float* __restrict__ A, const float* __restrict__ B,
        float* __restrict__ C, int M, int K, int Nn,
        const float* __restrict__ sc, const float* __restrict__ sh,
        const float* __restrict__ asrc, const float* __restrict__ adst,
        float* __restrict__ als, float* __restrict__ ald) {
    constexpr int TNB = 16 * NR;
    __shared__ float As[TK][TM + 4];
    __shared__ float Bs[TK][TNB];
    int t  = threadIdx.x;
    int m0 = blockIdx.y * TM;
    int n0 = blockIdx.x * TNB;
    int tx = t & 15;   // 16 col groups (xNR)
    int ty = t >> 4;   // 16 row groups (x8)
    float acc[8][NR];
#pragma unroll
    for (int i = 0; i < 8; i++)
#pragma unroll
        for (int j = 0; j < NR; j++) acc[i][j] = 0.f;

    for (int k0 = 0; k0 < K; k0 += TK) {
        // A tile: 128x16 = 512 float4, 2 per thread, stored transposed
#pragma unroll
        for (int i = 0; i < 2; i++) {
            int f  = t + i * 256;
            int r  = f >> 2;
            int c4 = (f & 3) * 4;
            int gm = m0 + r;
            float4 v = make_float4(0.f, 0.f, 0.f, 0.f);
            if (gm < M) v = *(const float4*)(A + (size_t)gm * K + k0 + c4);
            if (BNA) {
                v.x = fmaxf(v.x * sc[k0 + c4 + 0] + sh[k0 + c4 + 0], 0.f);
                v.y = fmaxf(v.y * sc[k0 + c4 + 1] + sh[k0 + c4 + 1], 0.f);
                v.z = fmaxf(v.z * sc[k0 + c4 + 2] + sh[k0 + c4 + 2], 0.f);
                v.w = fmaxf(v.w * sc[k0 + c4 + 3] + sh[k0 + c4 + 3], 0.f);
            }
            As[c4 + 0][r] = v.x; As[c4 + 1][r] = v.y;
            As[c4 + 2][r] = v.z; As[c4 + 3][r] = v.w;
        }
        // B tile: 16 x TNB = 64*NR float4, NR/4 per thread
#pragma unroll
        for (int i = 0; i < NR / 4; i++) {
            int f  = t + i * 256;
            int r  = f / (4 * NR);
            int c4 = (f % (4 * NR)) * 4;
            float4 v = *(const float4*)(B + (size_t)(k0 + r) * Nn + n0 + c4);
            *(float4*)&Bs[r][c4] = v;
        }
        __syncthreads();
#pragma unroll
        for (int k = 0; k < TK; k++) {
            float a_[8], b_[NR];
            *(float4*)(a_)     = *(float4*)&As[k][ty * 8];
            *(float4*)(a_ + 4) = *(float4*)&As[k][ty * 8 + 4];
#pragma unroll
            for (int j0 = 0; j0 < NR; j0 += 4)
                *(float4*)(b_ + j0) = *(float4*)&Bs[k][tx * NR + j0];
#pragma unroll
            for (int i = 0; i < 8; i++)
#pragma unroll
                for (int j = 0; j < NR; j++) acc[i][j] += a_[i] * b_[j];
        }
        __syncthreads();
    }

    // attention-vector slices for this thread's NR columns
    float as_r[NR], ad_r[NR];
    if (ALH) {
#pragma unroll
        for (int j = 0; j < NR; j++) {
            int col = n0 + tx * NR + j;
            as_r[j] = asrc[col];
            ad_r[j] = adst[col];
        }
    }

#pragma unroll
    for (int i = 0; i < 8; i++) {
        int gm = m0 + ty * 8 + i;
        if (gm < M) {
            float* cp = C + (size_t)gm * Nn + n0 + tx * NR;
#pragma unroll
            for (int j0 = 0; j0 < NR; j0 += 4)
                *(float4*)(cp + j0) = make_float4(acc[i][j0], acc[i][j0 + 1],
                                                  acc[i][j0 + 2], acc[i][j0 + 3]);
            if (ALH) {
                float s = 0.f, d = 0.f;
#pragma unroll
                for (int j = 0; j < NR; j++) { s += acc[i][j] * as_r[j]; d += acc[i][j] * ad_r[j]; }
                // lanes with the same ty are 16 consecutive lanes; whole block-col
                // group covers TNB columns
#pragma unroll
                for (int o = 8; o; o >>= 1) {
                    s += __shfl_down_sync(0xffffffffu, s, o, 16);
                    d += __shfl_down_sync(0xffffffffu, d, o, 16);
                }
                if (tx == 0) {
                    if (ALH == 4) {
                        int head = n0 >> 6;   // TNB=64: one head per block column
                        atomicAdd(&als[gm * 4 + head], s);
                        atomicAdd(&ald[gm * 4 + head], d);
                    } else {
                        atomicAdd(&als[gm], s);
                        atomicAdd(&ald[gm], d);
                    }
                }
            }
        }
    }
}

// ---------------- edge bucketing by dst (counting sort; built once, reused) ------
__global__ void hist_k(const int* __restrict__ ei, int E, int N, int* __restrict__ cnt) {
    int e = blockIdx.x * 256 + threadIdx.x;
    if (e >= E + N) return;
    int d = (e < E) ? ei[E + e] : (e - E);
    atomicAdd(&cnt[d], 1);
}

#define SCAN_T 1024
__global__ __launch_bounds__(SCAN_T) void scan_k(const int* __restrict__ cnt,
                                                 int* __restrict__ rowst, int N, int Etot) {
    __shared__ int part[SCAN_T];
    int t = threadIdx.x;
    int ch = (N + SCAN_T - 1) / SCAN_T;
    int s = 0;
    for (int k = 0; k < ch; k++) {
        int idx = t * ch + k;
        if (idx < N) s += cnt[idx];
    }
    part[t] = s;
    __syncthreads();
    for (int off = 1; off < SCAN_T; off <<= 1) {
        int v = (t >= off) ? part[t - off] : 0;
        __syncthreads();
        part[t] += v;
        __syncthreads();
    }
    int run = (t > 0) ? part[t - 1] : 0;
    for (int k = 0; k < ch; k++) {
        int idx = t * ch + k;
        if (idx < N) { rowst[idx] = run; run += cnt[idx]; }
    }
    if (t == SCAN_T - 1) rowst[N] = Etot;
}

__global__ void permute_k(const int* __restrict__ ei, int E, int N,
                          int* __restrict__ cursor, int* __restrict__ src_sorted) {
    int e = blockIdx.x * 256 + threadIdx.x;
    if (e >= E + N) return;
    int s, d;
    if (e < E) { s = ei[e]; d = ei[E + e]; } else { s = d = e - E; }
    int pos = atomicAdd(&cursor[d], 1);
    src_sorted[pos] = s;
}

__device__ __forceinline__ float lrelu(float v) { return v > 0.f ? v : 0.2f * v; }

// ---------------- fused GAT aggregation + BN stats, warp per dst node, H=4 -------
__global__ __launch_bounds__(256) void gat_agg1_k(
        const int* __restrict__ rowst, const int* __restrict__ src_sorted,
        const float* __restrict__ h, const float* __restrict__ als,
        const float* __restrict__ ald, float* __restrict__ out, int N,
        float* __restrict__ bnS, float* __restrict__ bnQ) {
    __shared__ float wsum[8][DFEAT];
    __shared__ float wsq[8][DFEAT];
    int t    = threadIdx.x;
    int wid  = t >> 5;
    int lane = t & 31;
    int w    = blockIdx.x * 8 + wid;
    bool act = w < N;
    int c0   = lane * 8;

    float o_[8];
#pragma unroll
    for (int k = 0; k < 8; k++) o_[k] = 0.f;

    if (act) {
        int start = rowst[w], end = rowst[w + 1];
        float4 aldv = *(const float4*)&ald[w * 4];
        int head = lane >> 3;
        float den0 = 0.f, den1 = 0.f, den2 = 0.f, den3 = 0.f;
        for (int base = start; base < end; base += 32) {
            int e = base + lane;
            int s = 0;
            float4 pe = make_float4(0.f, 0.f, 0.f, 0.f);
            if (e < end) {
                s = src_sorted[e];
                float4 av = *(const float4*)&als[s * 4];
                pe.x = __expf(lrelu(av.x + aldv.x));
                pe.y = __expf(lrelu(av.y + aldv.y));
                pe.z = __expf(lrelu(av.z + aldv.z));
                pe.w = __expf(lrelu(av.w + aldv.w));
                den0 += pe.x; den1 += pe.y; den2 += pe.z; den3 += pe.w;
            }
            int cnt = min(32, end - base);
            for (int j = 0; j < cnt; j++) {
                int   sj = __shfl_sync(0xffffffffu, s, j);
                float px = __shfl_sync(0xffffffffu, pe.x, j);
                float py = __shfl_sync(0xffffffffu, pe.y, j);
                float pz = __shfl_sync(0xffffffffu, pe.z, j);
                float pw = __shfl_sync(0xffffffffu, pe.w, j);
                float pej = (head < 2) ? (head == 0 ? px : py) : (head == 2 ? pz : pw);
                const float4* hp = (const float4*)(h + (size_t)sj * DFEAT + c0);
                float4 v0 = hp[0], v1 = hp[1];
                o_[0] += v0.x * pej; o_[1] += v0.y * pej;
                o_[2] += v0.z * pej; o_[3] += v0.w * pej;
                o_[4] += v1.x * pej; o_[5] += v1.y * pej;
                o_[6] += v1.z * pej; o_[7] += v1.w * pej;
            }
        }
#pragma unroll
        for (int o = 16; o; o >>= 1) {
            den0 += __shfl_xor_sync(0xffffffffu, den0, o);
            den1 += __shfl_xor_sync(0xffffffffu, den1, o);
            den2 += __shfl_xor_sync(0xffffffffu, den2, o);
            den3 += __shfl_xor_sync(0xffffffffu, den3, o);
        }
        float den = (head < 2) ? (head == 0 ? den0 : den1) : (head == 2 ? den2 : den3);
        float inv = 1.f / (den + 1e-16f);
#pragma unroll
        for (int k = 0; k < 8; k++) o_[k] *= inv;
        float* ob = out + (size_t)w * DFEAT + c0;
        *(float4*)ob       = make_float4(o_[0], o_[1], o_[2], o_[3]);
        *(float4*)(ob + 4) = make_float4(o_[4], o_[5], o_[6], o_[7]);
    }
    // stage per-warp row for BN stats (inactive warps contribute zeros)
#pragma unroll
    for (int k = 0; k < 8; k++) {
        wsum[wid][c0 + k] = o_[k];
        wsq[wid][c0 + k]  = o_[k] * o_[k];
    }
    __syncthreads();
    float s = 0.f, q = 0.f;
#pragma unroll
    for (int i = 0; i < 8; i++) { s += wsum[i][t]; q += wsq[i][t]; }
    atomicAdd(&bnS[t], s);
    atomicAdd(&bnQ[t], q);
}

// ---------------- fused GAT aggregation + BN stats, warp per dst node, H=1 -------
__global__ __launch_bounds__(256) void gat_agg2_k(
        const int* __restrict__ rowst, const int* __restrict__ src_sorted,
        const float* __restrict__ h, const float* __restrict__ als,
        const float* __restrict__ ald, float* __restrict__ out, int N,
        float* __restrict__ bnS, float* __restrict__ bnQ) {
    __shared__ float wsum[8][DFEAT];
    __shared__ float wsq[8][DFEAT];
    int t    = threadIdx.x;
    int wid  = t >> 5;
    int lane = t & 31;
    int w    = blockIdx.x * 8 + wid;
    bool act = w < N;
    int c0   = lane * 8;

    float o_[8];
#pragma unroll
    for (int k = 0; k < 8; k++) o_[k] = 0.f;

    if (act) {
        int start = rowst[w], end = rowst[w + 1];
        float aldd = ald[w];
        float den = 0.f;
        for (int base = start; base < end; base += 32) {
            int e = base + lane;
            int s = 0;
            float pe = 0.f;
            if (e < end) {
                s = src_sorted[e];
                pe = __expf(lrelu(als[s] + aldd));
                den += pe;
            }
            int cnt = min(32, end - base);
            for (int j = 0; j < cnt; j++) {
                int   sj  = __shfl_sync(0xffffffffu, s, j);
                float pej = __shfl_sync(0xffffffffu, pe, j);
                const float4* hp = (const float4*)(h + (size_t)sj * DFEAT + c0);
                float4 v0 = hp[0], v1 = hp[1];
                o_[0] += v0.x * pej; o_[1] += v0.y * pej;
                o_[2] += v0.z * pej; o_[3] += v0.w * pej;
                o_[4] += v1.x * pej; o_[5] += v1.y * pej;
                o_[6] += v1.z * pej; o_[7] += v1.w * pej;
            }
        }
#pragma unroll
        for (int o = 16; o; o >>= 1) den += __shfl_xor_sync(0xffffffffu, den, o);
        float inv = 1.f / (den + 1e-16f);
#pragma unroll
        for (int k = 0; k < 8; k++) o_[k] *= inv;
        float* ob = out + (size_t)w * DFEAT + c0;
        *(float4*)ob       = make_float4(o_[0], o_[1], o_[2], o_[3]);
        *(float4*)(ob + 4) = make_float4(o_[4], o_[5], o_[6], o_[7]);
    }
#pragma unroll
    for (int k = 0; k < 8; k++) {
        wsum[wid][c0 + k] = o_[k];
        wsq[wid][c0 + k]  = o_[k] * o_[k];
    }
    __syncthreads();
    float s = 0.f, q = 0.f;
#pragma unroll
    for (int i = 0; i < 8; i++) { s += wsum[i][t]; q += wsq[i][t]; }
    atomicAdd(&bnS[t], s);
    atomicAdd(&bnQ[t], q);
}

// ---------------- BN coefficient prep ----------------
__global__ void bnprep_k(const float* __restrict__ sum, const float* __restrict__ sumsq,
                         const float* __restrict__ g, const float* __restrict__ be,
                         float* __restrict__ sc, float* __restrict__ sh, int N) {
    int c = threadIdx.x;
    float invN = 1.f / (float)N;
    float m = sum[c] * invN;
    float v = sumsq[c] * invN - m * m;
    float s = g[c] * rsqrtf(v + 1e-5f);
    sc[c] = s;
    sh[c] = be[c] - m * s;
}

// ---- fused BN2-apply + relu + nodescore dot + pool accumulation (8 nodes/blk) ---
__global__ __launch_bounds__(256) void bn2_node_pool_k(
        float* __restrict__ x, const float* __restrict__ sc, const float* __restrict__ sh,
        const float* __restrict__ Wnode, const int* __restrict__ batch,
        float* __restrict__ poolS, float* __restrict__ out, int N) {
    __shared__ float spool[DFEAT];
    int t    = threadIdx.x;
    int wid  = t >> 5;
    int lane = t & 31;
    int n    = blockIdx.x * 8 + wid;
    int c0   = lane * 8;
    bool act = n < N;
    int gb0  = batch[min(blockIdx.x * 8, N - 1)];

    spool[t] = 0.f;
    __syncthreads();

    if (act) {
        float* xp = x + (size_t)n * DFEAT + c0;
        float4 v0 = *(float4*)xp, v1 = *(float4*)(xp + 4);
        float4 s0 = *(const float4*)&sc[c0], s1 = *(const float4*)&sc[c0 + 4];
        float4 h0 = *(const float4*)&sh[c0], h1 = *(const float4*)&sh[c0 + 4];
        float y[8];
        y[0] = fmaxf(v0.x * s0.x + h0.x, 0.f); y[1] = fmaxf(v0.y * s0.y + h0.y, 0.f);
        y[2] = fmaxf(v0.z * s0.z + h0.z, 0.f); y[3] = fmaxf(v0.w * s0.w + h0.w, 0.f);
        y[4] = fmaxf(v1.x * s1.x + h1.x, 0.f); y[5] = fmaxf(v1.y * s1.y + h1.y, 0.f);
        y[6] = fmaxf(v1.z * s1.z + h1.z, 0.f); y[7] = fmaxf(v1.w * s1.w + h1.w, 0.f);
        *(float4*)xp       = make_float4(y[0], y[1], y[2], y[3]);
        *(float4*)(xp + 4) = make_float4(y[4], y[5], y[6], y[7]);
        // node score dot
        float4 w0 = *(const float4*)&Wnode[c0], w1 = *(const float4*)&Wnode[c0 + 4];
        float dot = y[0]*w0.x + y[1]*w0.y + y[2]*w0.z + y[3]*w0.w
                  + y[4]*w1.x + y[5]*w1.y + y[6]*w1.z + y[7]*w1.w;
#pragma unroll
        for (int o = 16; o; o >>= 1) dot += __shfl_down_sync(0xffffffffu, dot, o);
        if (!lane) out[n] = dot;   // raw; s2 + bias in fixup
        // pool accumulation
        int g = batch[n];
        if (g == gb0) {
#pragma unroll
            for (int k = 0; k < 8; k++) atomicAdd(&spool[c0 + k], y[k]);
        } else {
#pragma unroll
            for (int k = 0; k < 8; k++) atomicAdd(&poolS[g * DFEAT + c0 + k], y[k]);
        }
    }
    __syncthreads();
    float pv = spool[t];
    if (pv != 0.f) atomicAdd(&poolS[gb0 * DFEAT + t], pv);
}

// ---------------- heads: block per graph; counts via binary search ---------------
__global__ __launch_bounds__(256) void heads_k(
        const float* __restrict__ xn, const int* __restrict__ target,
        const float* __restrict__ Wsh, const float* __restrict__ bsh,
        const float* __restrict__ Wnode,
        const float* __restrict__ Wtype, const float* __restrict__ btype,
        const float* __restrict__ Wcrit, const float* __restrict__ bcrit,
        const float* __restrict__ pool_sums, const int* __restrict__ batch,
        float* __restrict__ s2, float* __restrict__ out, int N) {
    __shared__ float gf[DFEAT];
    __shared__ float shm[DFEAT];
    __shared__ float part[8][6];
    __shared__ float cnt_sh;
    int b = blockIdx.x;
    int t = threadIdx.x;
    if (t == 0) {
        // count nodes with batch[i]==b (batch sorted ascending)
        int lo = 0, hi = N;
        while (lo < hi) { int mid = (lo + hi) >> 1; if (batch[mid] < b) lo = mid + 1; else hi = mid; }
        int L = lo;
        lo = 0; hi = N;
        while (lo < hi) { int mid = (lo + hi) >> 1; if (batch[mid] < b + 1) lo = mid + 1; else hi = mid; }
        cnt_sh = (float)(lo - L);
    }
    __syncthreads();
    gf[t] = pool_sums[b * DFEAT + t] / fmaxf(cnt_sh, 1.f);
    __syncthreads();
    float acc = bsh[t];
    for (int k = 0; k < DFEAT; k++) acc += gf[k] * Wsh[k * DFEAT + t];
    shm[t] = fmaxf(acc, 0.f);
    __syncthreads();

    int tn = target[b];
    float xv = xn[(size_t)tn * DFEAT + t];
    float v[6];
    v[0] = shm[t] * Wnode[256 + t];
    v[1] = shm[t] * Wcrit[t];
#pragma unroll
    for (int a = 0; a < 4; a++)
        v[2 + a] = shm[t] * Wtype[t * 4 + a] + xv * Wtype[(256 + t) * 4 + a];
#pragma unroll
    for (int o = 16; o; o >>= 1)
#pragma unroll
        for (int i = 0; i < 6; i++) v[i] += __shfl_down_sync(0xffffffffu, v[i], o);
    if ((t & 31) == 0)
#pragma unroll
        for (int i = 0; i < 6; i++) part[t >> 5][i] = v[i];
    __syncthreads();
    if (t == 0) {
        float r[6] = {0.f, 0.f, 0.f, 0.f, 0.f, 0.f};
        for (int w = 0; w < 8; w++)
#pragma unroll
            for (int i = 0; i < 6; i++) r[i] += part[w][i];
        s2[b] = r[0];
        out[N + 32 + b] = r[1] + bcrit[0];
#pragma unroll
        for (int a = 0; a < 4; a++) out[N + b * 4 + a] = r[2 + a] + btype[a];
    }
}

// ---------------- fixup: add s2[batch] + bnode to node scores ----------------
__global__ void fixup_k(float* __restrict__ out, const int* __restrict__ batch,
                        const float* __restrict__ s2, const float* __restrict__ bnode, int N) {
    int i = blockIdx.x * 256 + threadIdx.x;
    if (i < N) out[i] += s2[batch[i]] + bnode[0];
}

// ---------------- host orchestration ----------------
extern "C" void kernel_launch(void* const* d_in, const int* in_sizes, int n_in,
                              void* d_out, int out_size) {
    const float* x      = (const float*)d_in[0];
    const int*   ei     = (const int*)d_in[1];
    const int*   batch  = (const int*)d_in[2];
    const int*   target = (const int*)d_in[3];
    const float* W1     = (const float*)d_in[4];
    const float* a1s    = (const float*)d_in[5];
    const float* a1d    = (const float*)d_in[6];
    const float* W2     = (const float*)d_in[8];
    const float* a2s    = (const float*)d_in[9];
    const float* a2d    = (const float*)d_in[10];
    const float* g1     = (const float*)d_in[12];
    const float* be1    = (const float*)d_in[13];
    const float* g2     = (const float*)d_in[14];
    const float* be2    = (const float*)d_in[15];
    const float* Wsh    = (const float*)d_in[16];
    const float* bsh    = (const float*)d_in[17];
    const float* Wnode  = (const float*)d_in[18];
    const float* bnode  = (const float*)d_in[19];
    const float* Wtype  = (const float*)d_in[20];
    const float* btype  = (const float*)d_in[21];
    const float* Wcrit  = (const float*)d_in[22];
    const float* bcrit  = (const float*)d_in[23];
    float* out = (float*)d_out;

    int N = in_sizes[2];
    int F = in_sizes[0] / N;
    int E = in_sizes[1] / 2;
    int Etot = E + N;

    float *bufA, *bufB, *als1, *ald1, *als2, *ald2;
    float *bnS, *bnQ, *sc1, *sh1, *sc2, *sh2, *poolS, *s2;
    int *cnt, *rowst, *cursor, *src_sorted;
    cudaGetSymbolAddress((void**)&bufA,  g_bufA);
    cudaGetSymbolAddress((void**)&bufB,  g_bufB);
    cudaGetSymbolAddress((void**)&als1,  g_als1);
    cudaGetSymbolAddress((void**)&ald1,  g_ald1);
    cudaGetSymbolAddress((void**)&als2,  g_als2);
    cudaGetSymbolAddress((void**)&ald2,  g_ald2);
    cudaGetSymbolAddress((void**)&cnt,   g_cnt);
    cudaGetSymbolAddress((void**)&rowst, g_rowst);
    cudaGetSymbolAddress((void**)&cursor, g_cursor);
    cudaGetSymbolAddress((void**)&src_sorted, g_src_sorted);
    cudaGetSymbolAddress((void**)&bnS,   g_bn_sum);
    cudaGetSymbolAddress((void**)&bnQ,   g_bn_sumsq);
    cudaGetSymbolAddress((void**)&sc1,   g_sc1);
    cudaGetSymbolAddress((void**)&sh1,   g_sh1);
    cudaGetSymbolAddress((void**)&sc2,   g_sc2);
    cudaGetSymbolAddress((void**)&sh2,   g_sh2);
    cudaGetSymbolAddress((void**)&poolS, g_pool_sum);
    cudaGetSymbolAddress((void**)&s2,    g_s2);

    // ---- zero init (async memsets; graph-capturable) ----
    cudaMemsetAsync(cnt,   0, (size_t)(N + 1) * sizeof(int));
    cudaMemsetAsync(als1,  0, (size_t)N * H1HEADS * sizeof(float));
    cudaMemsetAsync(ald1,  0, (size_t)N * H1HEADS * sizeof(float));
    cudaMemsetAsync(als2,  0, (size_t)N * sizeof(float));
    cudaMemsetAsync(ald2,  0, (size_t)N * sizeof(float));
    cudaMemsetAsync(poolS, 0, NGRAPHS * DFEAT * sizeof(float));
    cudaMemsetAsync(bnS,   0, DFEAT * sizeof(float));
    cudaMemsetAsync(bnQ,   0, DFEAT * sizeof(float));

    // ---- edge bucketing (shared by both layers) ----
    hist_k<<<cdiv(Etot, 256), 256>>>(ei, E, N, cnt);
    scan_k<<<1, SCAN_T>>>(cnt, rowst, N, Etot);
    cudaMemcpyAsync(cursor, rowst, (size_t)N * sizeof(int), cudaMemcpyDeviceToDevice);
    permute_k<<<cdiv(Etot, 256), 256>>>(ei, E, N, cursor, src_sorted);

    // ---- GAT layer 1: GEMM(128x64 tile, +al1 epilogue) -> agg(+BN1 stats) ----
    {
        dim3 grid(DFEAT / 64, cdiv(N, TM));
        sgemm_k<4, 4, false><<<grid, 256>>>(x, W1, bufA, N, F, DFEAT,
                                            nullptr, nullptr, a1s, a1d, als1, ald1);
    }
    gat_agg1_k<<<cdiv(N, 8), 256>>>(rowst, src_sorted, bufA, als1, ald1, bufB, N, bnS, bnQ);
    bnprep_k<<<1, 256>>>(bnS, bnQ, g1, be1, sc1, sh1, N);

    // ---- GAT layer 2: GEMM(128x128 tile, BN1 fused on A, +al2) -> agg(+BN2 stats)
    {
        dim3 grid(DFEAT / 128, cdiv(N, TM));
        sgemm_k<8, 1, true><<<grid, 256>>>(bufB, W2, bufA, N, DFEAT, DFEAT,
                                           sc1, sh1, a2s, a2d, als2, ald2);
    }
    cudaMemsetAsync(bnS, 0, DFEAT * sizeof(float));
    cudaMemsetAsync(bnQ, 0, DFEAT * sizeof(float));
    gat_agg2_k<<<cdiv(N, 8), 256>>>(rowst, src_sorted, bufA, als2, ald2, bufB, N, bnS, bnQ);
    bnprep_k<<<1, 256>>>(bnS, bnQ, g2, be2, sc2, sh2, N);

    // ---- BN2 apply + nodescore dot + pool accumulation ----
    bn2_node_pool_k<<<cdiv(N, 8), 256>>>(bufB, sc2, sh2, Wnode, batch, poolS, out, N);

    // ---- heads + fixup ----
    heads_k<<<NGRAPHS, 256>>>(bufB, target, Wsh, bsh, Wnode, Wtype, btype, Wcrit, bcrit,
                              poolS, batch, s2, out, N);
    fixup_k<<<cdiv(N, 256), 256>>>(out, batch, s2, bnode, N);
}

// round 9
// speedup vs baseline: 1.8024x; 1.2062x over previous
#include <cuda_runtime.h>
#include <cstdint>

// Problem constants (fixed shapes for this dataset)
#define NNODES   50000
#define DFEAT    256
#define H1HEADS  4
#define NGRAPHS  8
#define EMAX     400000
#define ETOTMAX  (EMAX + NNODES)

// ---------------- scratch (static device globals; no allocation) ----------------
__device__ float g_bufA[NNODES * DFEAT];   // linear-layer output (h1 / h2)
__device__ float g_bufB[NNODES * DFEAT];   // aggregation output
__device__ float g_als1[NNODES * H1HEADS];
__device__ float g_ald1[NNODES * H1HEADS];
__device__ float g_als2[NNODES];
__device__ float g_ald2[NNODES];
__device__ int   g_cnt[NNODES + 1];
__device__ int   g_rowst[NNODES + 1];
__device__ int   g_cursor[NNODES];
__device__ int   g_src_sorted[ETOTMAX];
__device__ float g_bn_sum[DFEAT];
__device__ float g_bn_sumsq[DFEAT];
__device__ float g_sc1[DFEAT];
__device__ float g_sh1[DFEAT];
__device__ float g_sc2[DFEAT];
__device__ float g_sh2[DFEAT];
__device__ float g_pool_sum[NGRAPHS * DFEAT];
__device__ float g_s2[NGRAPHS];

static inline int cdiv(int a, int b) { return (a + b - 1) / b; }

// ---------------- tf32 helpers ----------------
__device__ __forceinline__ uint32_t f2tf32(float x) {
    uint32_t u;
    asm("cvt.rna.tf32.f32 %0, %1;" : "=r"(u) : "f"(x));
    return u;
}

__device__ __forceinline__ void mma_tf32(float* d, const uint32_t* a, const uint32_t* b) {
    asm volatile(
        "mma.sync.aligned.m16n8k8.row.col.f32.tf32.tf32.f32 "
        "{%0,%1,%2,%3}, {%4,%5,%6,%7}, {%8,%9}, {%0,%1,%2,%3};"
        : "+f"(d[0]), "+f"(d[1]), "+f"(d[2]), "+f"(d[3])
        : "r"(a[0]), "r"(a[1]), "r"(a[2]), "r"(a[3]), "r"(b[0]), "r"(b[1]));
}

// ---------------- tf32 MMA GEMM: 128x128 block, warps 4x2 (each 32x64) ----------
// C[M,Nn] = A[M,K] @ B[K,Nn]; BNA: y=relu(a*sc[k]+sh[k]) on A load;
// ALH1: single-head attention-dot epilogue into als/ald.
#define MTK 16
template <bool BNA, bool ALH1>
__global__ __launch_bounds__(256) void mma_gemm_k(
        const float* __restrict__ A, const float* __restrict__ B,
        float* __restrict__ C, int M, int K, int Nn,
        const float* __restrict__ sc, const float* __restrict__ sh,
        const float* __restrict__ asrc, const float* __restrict__ adst,
        float* __restrict__ als, float* __restrict__ ald) {
    __shared__ uint32_t As[MTK][128 + 8];   // tf32 bits, [k][m], pad 8
    __shared__ uint32_t Bs[MTK][128 + 8];   // tf32 bits, [k][n], pad 8
    int t    = threadIdx.x;
    int lane = t & 31;
    int wid  = t >> 5;
    int wm   = (wid >> 1) * 32;   // warp row offset: 0,32,64,96
    int wn   = (wid & 1) * 64;    // warp col offset: 0,64
    int m0   = blockIdx.y * 128;
    int n0   = blockIdx.x * 128;
    int g    = lane >> 2;         // 0..7
    int t4   = lane & 3;          // 0..3

    float acc[2][8][4];
#pragma unroll
    for (int mt = 0; mt < 2; mt++)
#pragma unroll
        for (int nt = 0; nt < 8; nt++)
#pragma unroll
            for (int i = 0; i < 4; i++) acc[mt][nt][i] = 0.f;

    for (int k0 = 0; k0 < K; k0 += MTK) {
        // A tile: 128 rows x 16 cols, 2 float4 per thread, stored transposed [k][m]
#pragma unroll
        for (int i = 0; i < 2; i++) {
            int f  = t + i * 256;
            int r  = f >> 2;
            int c4 = (f & 3) * 4;
            int gm = m0 + r;
            float4 v = make_float4(0.f, 0.f, 0.f, 0.f);
            if (gm < M) v = *(const float4*)(A + (size_t)gm * K + k0 + c4);
            if (BNA) {
                v.x = fmaxf(v.x * sc[k0 + c4 + 0] + sh[k0 + c4 + 0], 0.f);
                v.y = fmaxf(v.y * sc[k0 + c4 + 1] + sh[k0 + c4 + 1], 0.f);
                v.z = fmaxf(v.z * sc[k0 + c4 + 2] + sh[k0 + c4 + 2], 0.f);
                v.w = fmaxf(v.w * sc[k0 + c4 + 3] + sh[k0 + c4 + 3], 0.f);
            }
            As[c4 + 0][r] = f2tf32(v.x); As[c4 + 1][r] = f2tf32(v.y);
            As[c4 + 2][r] = f2tf32(v.z); As[c4 + 3][r] = f2tf32(v.w);
        }
        // B tile: 16 rows x 128 cols, 2 float4 per thread, [k][n]
#pragma unroll
        for (int i = 0; i < 2; i++) {
            int f  = t + i * 256;
            int r  = f >> 5;
            int c4 = (f & 31) * 4;
            float4 v = *(const float4*)(B + (size_t)(k0 + r) * Nn + n0 + c4);
            Bs[r][c4 + 0] = f2tf32(v.x); Bs[r][c4 + 1] = f2tf32(v.y);
            Bs[r][c4 + 2] = f2tf32(v.z); Bs[r][c4 + 3] = f2tf32(v.w);
        }
        __syncthreads();
#pragma unroll
        for (int ks = 0; ks < MTK; ks += 8) {
            uint32_t af[2][4];
#pragma unroll
            for (int mt = 0; mt < 2; mt++) {
                int mr = wm + mt * 16;
                af[mt][0] = As[ks + t4][mr + g];
                af[mt][1] = As[ks + t4][mr + g + 8];
                af[mt][2] = As[ks + t4 + 4][mr + g];
                af[mt][3] = As[ks + t4 + 4][mr + g + 8];
            }
            uint32_t bf[8][2];
#pragma unroll
            for (int nt = 0; nt < 8; nt++) {
                int nc = wn + nt * 8 + g;
                bf[nt][0] = Bs[ks + t4][nc];
                bf[nt][1] = Bs[ks + t4 + 4][nc];
            }
#pragma unroll
            for (int mt = 0; mt < 2; mt++)
#pragma unroll
                for (int nt = 0; nt < 8; nt++)
                    mma_tf32(acc[mt][nt], af[mt], bf[nt]);
        }
        __syncthreads();
    }

    // ---- epilogue: store C (+ optional attention dots) ----
#pragma unroll
    for (int mt = 0; mt < 2; mt++) {
        int gm0 = m0 + wm + mt * 16 + g;
        int gm1 = gm0 + 8;
        float s0 = 0.f, d0 = 0.f, s1 = 0.f, d1 = 0.f;
#pragma unroll
        for (int nt = 0; nt < 8; nt++) {
            int cb = n0 + wn + nt * 8 + 2 * t4;
            if (gm0 < M)
                *(float2*)(C + (size_t)gm0 * Nn + cb) = make_float2(acc[mt][nt][0], acc[mt][nt][1]);
            if (gm1 < M)
                *(float2*)(C + (size_t)gm1 * Nn + cb) = make_float2(acc[mt][nt][2], acc[mt][nt][3]);
            if (ALH1) {
                float w0s = asrc[cb], w1s = asrc[cb + 1];
                float w0d = adst[cb], w1d = adst[cb + 1];
                s0 += acc[mt][nt][0] * w0s + acc[mt][nt][1] * w1s;
                d0 += acc[mt][nt][0] * w0d + acc[mt][nt][1] * w1d;
                s1 += acc[mt][nt][2] * w0s + acc[mt][nt][3] * w1s;
                d1 += acc[mt][nt][2] * w0d + acc[mt][nt][3] * w1d;
            }
        }
        if (ALH1) {
            // reduce over the 4 contiguous lanes sharing g (t4 = 0..3)
#pragma unroll
            for (int o = 2; o; o >>= 1) {
                s0 += __shfl_down_sync(0xffffffffu, s0, o, 4);
                d0 += __shfl_down_sync(0xffffffffu, d0, o, 4);
                s1 += __shfl_down_sync(0xffffffffu, s1, o, 4);
                d1 += __shfl_down_sync(0xffffffffu, d1, o, 4);
            }
            if (t4 == 0) {
                if (gm0 < M) { atomicAdd(&als[gm0], s0); atomicAdd(&ald[gm0], d0); }
                if (gm1 < M) { atomicAdd(&als[gm1], s1); atomicAdd(&ald[gm1], d1); }
            }
        }
    }
}

// ---------------- FFMA SGEMM 128x64 (kept for GEMM1, K=64) ----------------------
#define TM 128
#define TK 16
__global__ __launch_bounds__(256) void sgemm1_k(
        const float* __restrict__ A, const float* __restrict__ B,
        float* __restrict__ C, int M, int K, int Nn,
        const float* __restrict__ asrc, const float* __restrict__ adst,
        float* __restrict__ als, float* __restrict__ ald) {
    constexpr int NR = 4;
    constexpr int TNB = 16 * NR;
    __shared__ float As[TK][TM + 4];
    __shared__ float Bs[TK][TNB];
    int t  = threadIdx.x;
    int m0 = blockIdx.y * TM;
    int n0 = blockIdx.x * TNB;
    int tx = t & 15;
    int ty = t >> 4;
    float acc[8][NR];
#pragma unroll
    for (int i = 0; i < 8; i++)
#pragma unroll
        for (int j = 0; j < NR; j++) acc[i][j] = 0.f;

    for (int k0 = 0; k0 < K; k0 += TK) {
#pragma unroll
        for (int i = 0; i < 2; i++) {
            int f  = t + i * 256;
            int r  = f >> 2;
            int c4 = (f & 3) * 4;
            int gm = m0 + r;
            float4 v = make_float4(0.f, 0.f, 0.f, 0.f);
            if (gm < M) v = *(const float4*)(A + (size_t)gm * K + k0 + c4);
            As[c4 + 0][r] = v.x; As[c4 + 1][r] = v.y;
            As[c4 + 2][r] = v.z; As[c4 + 3][r] = v.w;
        }
        {
            int r  = t >> 4;
            int c4 = (t & 15) * 4;
            float4 v = *(const float4*)(B + (size_t)(k0 + r) * Nn + n0 + c4);
            *(float4*)&Bs[r][c4] = v;
        }
        __syncthreads();
#pragma unroll
        for (int k = 0; k < TK; k++) {
            float a_[8], b_[NR];
            *(float4*)(a_)     = *(float4*)&As[k][ty * 8];
            *(float4*)(a_ + 4) = *(float4*)&As[k][ty * 8 + 4];
            *(float4*)(b_)     = *(float4*)&Bs[k][tx * NR];
#pragma unroll
            for (int i = 0; i < 8; i++)
#pragma unroll
                for (int j = 0; j < NR; j++) acc[i][j] += a_[i] * b_[j];
        }
        __syncthreads();
    }

    float as_r[NR], ad_r[NR];
#pragma unroll
    for (int j = 0; j < NR; j++) {
        int col = n0 + tx * NR + j;
        as_r[j] = asrc[col];
        ad_r[j] = adst[col];
    }

#pragma unroll
    for (int i = 0; i < 8; i++) {
        int gm = m0 + ty * 8 + i;
        if (gm < M) {
            float* cp = C + (size_t)gm * Nn + n0 + tx * NR;
            *(float4*)cp = make_float4(acc[i][0], acc[i][1], acc[i][2], acc[i][3]);
            float s = 0.f, d = 0.f;
#pragma unroll
            for (int j = 0; j < NR; j++) { s += acc[i][j] * as_r[j]; d += acc[i][j] * ad_r[j]; }
#pragma unroll
            for (int o = 8; o; o >>= 1) {
                s += __shfl_down_sync(0xffffffffu, s, o, 16);
                d += __shfl_down_sync(0xffffffffu, d, o, 16);
            }
            if (tx == 0) {
                int head = n0 >> 6;   // TNB=64: one head per block column
                atomicAdd(&als[gm * 4 + head], s);
                atomicAdd(&ald[gm * 4 + head], d);
            }
        }
    }
}

// ---------------- edge bucketing by dst (counting sort; built once, reused) ------
__global__ void hist_k(const int* __restrict__ ei, int E, int N, int* __restrict__ cnt) {
    int e = blockIdx.x * 256 + threadIdx.x;
    if (e >= E + N) return;
    int d = (e < E) ? ei[E + e] : (e - E);
    atomicAdd(&cnt[d], 1);
}

#define SCAN_T 1024
__global__ __launch_bounds__(SCAN_T) void scan_k(const int* __restrict__ cnt,
                                                 int* __restrict__ rowst, int N, int Etot) {
    __shared__ int part[SCAN_T];
    int t = threadIdx.x;
    int ch = (N + SCAN_T - 1) / SCAN_T;
    int s = 0;
    for (int k = 0; k < ch; k++) {
        int idx = t * ch + k;
        if (idx < N) s += cnt[idx];
    }
    part[t] = s;
    __syncthreads();
    for (int off = 1; off < SCAN_T; off <<= 1) {
        int v = (t >= off) ? part[t - off] : 0;
        __syncthreads();
        part[t] += v;
        __syncthreads();
    }
    int run = (t > 0) ? part[t - 1] : 0;
    for (int k = 0; k < ch; k++) {
        int idx = t * ch + k;
        if (idx < N) { rowst[idx] = run; run += cnt[idx]; }
    }
    if (t == SCAN_T - 1) rowst[N] = Etot;
}

__global__ void permute_k(const int* __restrict__ ei, int E, int N,
                          int* __restrict__ cursor, int* __restrict__ src_sorted) {
    int e = blockIdx.x * 256 + threadIdx.x;
    if (e >= E + N) return;
    int s, d;
    if (e < E) { s = ei[e]; d = ei[E + e]; } else { s = d = e - E; }
    int pos = atomicAdd(&cursor[d], 1);
    src_sorted[pos] = s;
}

__device__ __forceinline__ float lrelu(float v) { return v > 0.f ? v : 0.2f * v; }

// ---------------- fused GAT aggregation + BN stats, warp per dst node, H=4 -------
__global__ __launch_bounds__(256) void gat_agg1_k(
        const int* __restrict__ rowst, const int* __restrict__ src_sorted,
        const float* __restrict__ h, const float* __restrict__ als,
        const float* __restrict__ ald, float* __restrict__ out, int N,
        float* __restrict__ bnS, float* __restrict__ bnQ) {
    __shared__ float wsum[8][DFEAT];
    __shared__ float wsq[8][DFEAT];
    int t    = threadIdx.x;
    int wid  = t >> 5;
    int lane = t & 31;
    int w    = blockIdx.x * 8 + wid;
    bool act = w < N;
    int c0   = lane * 8;

    float o_[8];
#pragma unroll
    for (int k = 0; k < 8; k++) o_[k] = 0.f;

    if (act) {
        int start = rowst[w], end = rowst[w + 1];
        float4 aldv = *(const float4*)&ald[w * 4];
        int head = lane >> 3;
        float den0 = 0.f, den1 = 0.f, den2 = 0.f, den3 = 0.f;
        for (int base = start; base < end; base += 32) {
            int e = base + lane;
            int s = 0;
            float4 pe = make_float4(0.f, 0.f, 0.f, 0.f);
            if (e < end) {
                s = src_sorted[e];
                float4 av = *(const float4*)&als[s * 4];
                pe.x = __expf(lrelu(av.x + aldv.x));
                pe.y = __expf(lrelu(av.y + aldv.y));
                pe.z = __expf(lrelu(av.z + aldv.z));
                pe.w = __expf(lrelu(av.w + aldv.w));
                den0 += pe.x; den1 += pe.y; den2 += pe.z; den3 += pe.w;
            }
            int cnt = min(32, end - base);
            for (int j = 0; j < cnt; j++) {
                int   sj = __shfl_sync(0xffffffffu, s, j);
                float px = __shfl_sync(0xffffffffu, pe.x, j);
                float py = __shfl_sync(0xffffffffu, pe.y, j);
                float pz = __shfl_sync(0xffffffffu, pe.z, j);
                float pw = __shfl_sync(0xffffffffu, pe.w, j);
                float pej = (head < 2) ? (head == 0 ? px : py) : (head == 2 ? pz : pw);
                const float4* hp = (const float4*)(h + (size_t)sj * DFEAT + c0);
                float4 v0 = hp[0], v1 = hp[1];
                o_[0] += v0.x * pej; o_[1] += v0.y * pej;
                o_[2] += v0.z * pej; o_[3] += v0.w * pej;
                o_[4] += v1.x * pej; o_[5] += v1.y * pej;
                o_[6] += v1.z * pej; o_[7] += v1.w * pej;
            }
        }
#pragma unroll
        for (int o = 16; o; o >>= 1) {
            den0 += __shfl_xor_sync(0xffffffffu, den0, o);
            den1 += __shfl_xor_sync(0xffffffffu, den1, o);
            den2 += __shfl_xor_sync(0xffffffffu, den2, o);
            den3 += __shfl_xor_sync(0xffffffffu, den3, o);
        }
        float den = (head < 2) ? (head == 0 ? den0 : den1) : (head == 2 ? den2 : den3);
        float inv = 1.f / (den + 1e-16f);
#pragma unroll
        for (int k = 0; k < 8; k++) o_[k] *= inv;
        float* ob = out + (size_t)w * DFEAT + c0;
        *(float4*)ob       = make_float4(o_[0], o_[1], o_[2], o_[3]);
        *(float4*)(ob + 4) = make_float4(o_[4], o_[5], o_[6], o_[7]);
    }
#pragma unroll
    for (int k = 0; k < 8; k++) {
        wsum[wid][c0 + k] = o_[k];
        wsq[wid][c0 + k]  = o_[k] * o_[k];
    }
    __syncthreads();
    float s = 0.f, q = 0.f;
#pragma unroll
    for (int i = 0; i < 8; i++) { s += wsum[i][t]; q += wsq[i][t]; }
    atomicAdd(&bnS[t], s);
    atomicAdd(&bnQ[t], q);
}

// ---------------- fused GAT aggregation + BN stats, warp per dst node, H=1 -------
__global__ __launch_bounds__(256) void gat_agg2_k(
        const int* __restrict__ rowst, const int* __restrict__ src_sorted,
        const float* __restrict__ h, const float* __restrict__ als,
        const float* __restrict__ ald, float* __restrict__ out, int N,
        float* __restrict__ bnS, float* __restrict__ bnQ) {
    __shared__ float wsum[8][DFEAT];
    __shared__ float wsq[8][DFEAT];
    int t    = threadIdx.x;
    int wid  = t >> 5;
    int lane = t & 31;
    int w    = blockIdx.x * 8 + wid;
    bool act = w < N;
    int c0   = lane * 8;

    float o_[8];
#pragma unroll
    for (int k = 0; k < 8; k++) o_[k] = 0.f;

    if (act) {
        int start = rowst[w], end = rowst[w + 1];
        float aldd = ald[w];
        float den = 0.f;
        for (int base = start; base < end; base += 32) {
            int e = base + lane;
            int s = 0;
            float pe = 0.f;
            if (e < end) {
                s = src_sorted[e];
                pe = __expf(lrelu(als[s] + aldd));
                den += pe;
            }
            int cnt = min(32, end - base);
            for (int j = 0; j < cnt; j++) {
                int   sj  = __shfl_sync(0xffffffffu, s, j);
                float pej = __shfl_sync(0xffffffffu, pe, j);
                const float4* hp = (const float4*)(h + (size_t)sj * DFEAT + c0);
                float4 v0 = hp[0], v1 = hp[1];
                o_[0] += v0.x * pej; o_[1] += v0.y * pej;
                o_[2] += v0.z * pej; o_[3] += v0.w * pej;
                o_[4] += v1.x * pej; o_[5] += v1.y * pej;
                o_[6] += v1.z * pej; o_[7] += v1.w * pej;
            }
        }
#pragma unroll
        for (int o = 16; o; o >>= 1) den += __shfl_xor_sync(0xffffffffu, den, o);
        float inv = 1.f / (den + 1e-16f);
#pragma unroll
        for (int k = 0; k < 8; k++) o_[k] *= inv;
        float* ob = out + (size_t)w * DFEAT + c0;
        *(float4*)ob       = make_float4(o_[0], o_[1], o_[2], o_[3]);
        *(float4*)(ob + 4) = make_float4(o_[4], o_[5], o_[6], o_[7]);
    }
#pragma unroll
    for (int k = 0; k < 8; k++) {
        wsum[wid][c0 + k] = o_[k];
        wsq[wid][c0 + k]  = o_[k] * o_[k];
    }
    __syncthreads();
    float s = 0.f, q = 0.f;
#pragma unroll
    for (int i = 0; i < 8; i++) { s += wsum[i][t]; q += wsq[i][t]; }
    atomicAdd(&bnS[t], s);
    atomicAdd(&bnQ[t], q);
}

// ---------------- BN coefficient prep ----------------
__global__ void bnprep_k(const float* __restrict__ sum, const float* __restrict__ sumsq,
                         const float* __restrict__ g, const float* __restrict__ be,
                         float* __restrict__ sc, float* __restrict__ sh, int N) {
    int c = threadIdx.x;
    float invN = 1.f / (float)N;
    float m = sum[c] * invN;
    float v = sumsq[c] * invN - m * m;
    float s = g[c] * rsqrtf(v + 1e-5f);
    sc[c] = s;
    sh[c] = be[c] - m * s;
}

// ---- fused BN2-apply + relu + nodescore dot + pool accumulation (8 nodes/blk) ---
__global__ __launch_bounds__(256) void bn2_node_pool_k(
        float* __restrict__ x, const float* __restrict__ sc, const float* __restrict__ sh,
        const float* __restrict__ Wnode, const int* __restrict__ batch,
        float* __restrict__ poolS, float* __restrict__ out, int N) {
    __shared__ float spool[DFEAT];
    int t    = threadIdx.x;
    int wid  = t >> 5;
    int lane = t & 31;
    int n    = blockIdx.x * 8 + wid;
    int c0   = lane * 8;
    bool act = n < N;
    int gb0  = batch[min(blockIdx.x * 8, N - 1)];

    spool[t] = 0.f;
    __syncthreads();

    if (act) {
        float* xp = x + (size_t)n * DFEAT + c0;
        float4 v0 = *(float4*)xp, v1 = *(float4*)(xp + 4);
        float4 s0 = *(const float4*)&sc[c0], s1 = *(const float4*)&sc[c0 + 4];
        float4 h0 = *(const float4*)&sh[c0], h1 = *(const float4*)&sh[c0 + 4];
        float y[8];
        y[0] = fmaxf(v0.x * s0.x + h0.x, 0.f); y[1] = fmaxf(v0.y * s0.y + h0.y, 0.f);
        y[2] = fmaxf(v0.z * s0.z + h0.z, 0.f); y[3] = fmaxf(v0.w * s0.w + h0.w, 0.f);
        y[4] = fmaxf(v1.x * s1.x + h1.x, 0.f); y[5] = fmaxf(v1.y * s1.y + h1.y, 0.f);
        y[6] = fmaxf(v1.z * s1.z + h1.z, 0.f); y[7] = fmaxf(v1.w * s1.w + h1.w, 0.f);
        *(float4*)xp       = make_float4(y[0], y[1], y[2], y[3]);
        *(float4*)(xp + 4) = make_float4(y[4], y[5], y[6], y[7]);
        float4 w0 = *(const float4*)&Wnode[c0], w1 = *(const float4*)&Wnode[c0 + 4];
        float dot = y[0]*w0.x + y[1]*w0.y + y[2]*w0.z + y[3]*w0.w
                  + y[4]*w1.x + y[5]*w1.y + y[6]*w1.z + y[7]*w1.w;
#pragma unroll
        for (int o = 16; o; o >>= 1) dot += __shfl_down_sync(0xffffffffu, dot, o);
        if (!lane) out[n] = dot;   // raw; s2 + bias in fixup
        int g = batch[n];
        if (g == gb0) {
#pragma unroll
            for (int k = 0; k < 8; k++) atomicAdd(&spool[c0 + k], y[k]);
        } else {
#pragma unroll
            for (int k = 0; k < 8; k++) atomicAdd(&poolS[g * DFEAT + c0 + k], y[k]);
        }
    }
    __syncthreads();
    float pv = spool[t];
    if (pv != 0.f) atomicAdd(&poolS[gb0 * DFEAT + t], pv);
}

// ---------------- heads: block per graph; counts via binary search ---------------
__global__ __launch_bounds__(256) void heads_k(
        const float* __restrict__ xn, const int* __restrict__ target,
        const float* __restrict__ Wsh, const float* __restrict__ bsh,
        const float* __restrict__ Wnode,
        const float* __restrict__ Wtype, const float* __restrict__ btype,
        const float* __restrict__ Wcrit, const float* __restrict__ bcrit,
        const float* __restrict__ pool_sums, const int* __restrict__ batch,
        float* __restrict__ s2, float* __restrict__ out, int N) {
    __shared__ float gf[DFEAT];
    __shared__ float shm[DFEAT];
    __shared__ float part[8][6];
    __shared__ float cnt_sh;
    int b = blockIdx.x;
    int t = threadIdx.x;
    if (t == 0) {
        int lo = 0, hi = N;
        while (lo < hi) { int mid = (lo + hi) >> 1; if (batch[mid] < b) lo = mid + 1; else hi = mid; }
        int L = lo;
        lo = 0; hi = N;
        while (lo < hi) { int mid = (lo + hi) >> 1; if (batch[mid] < b + 1) lo = mid + 1; else hi = mid; }
        cnt_sh = (float)(lo - L);
    }
    __syncthreads();
    gf[t] = pool_sums[b * DFEAT + t] / fmaxf(cnt_sh, 1.f);
    __syncthreads();
    float acc = bsh[t];
    for (int k = 0; k < DFEAT; k++) acc += gf[k] * Wsh[k * DFEAT + t];
    shm[t] = fmaxf(acc, 0.f);
    __syncthreads();

    int tn = target[b];
    float xv = xn[(size_t)tn * DFEAT + t];
    float v[6];
    v[0] = shm[t] * Wnode[256 + t];
    v[1] = shm[t] * Wcrit[t];
#pragma unroll
    for (int a = 0; a < 4; a++)
        v[2 + a] = shm[t] * Wtype[t * 4 + a] + xv * Wtype[(256 + t) * 4 + a];
#pragma unroll
    for (int o = 16; o; o >>= 1)
#pragma unroll
        for (int i = 0; i < 6; i++) v[i] += __shfl_down_sync(0xffffffffu, v[i], o);
    if ((t & 31) == 0)
#pragma unroll
        for (int i = 0; i < 6; i++) part[t >> 5][i] = v[i];
    __syncthreads();
    if (t == 0) {
        float r[6] = {0.f, 0.f, 0.f, 0.f, 0.f, 0.f};
        for (int w = 0; w < 8; w++)
#pragma unroll
            for (int i = 0; i < 6; i++) r[i] += part[w][i];
        s2[b] = r[0];
        out[N + 32 + b] = r[1] + bcrit[0];
#pragma unroll
        for (int a = 0; a < 4; a++) out[N + b * 4 + a] = r[2 + a] + btype[a];
    }
}

// ---------------- fixup: add s2[batch] + bnode to node scores ----------------
__global__ void fixup_k(float* __restrict__ out, const int* __restrict__ batch,
                        const float* __restrict__ s2, const float* __restrict__ bnode, int N) {
    int i = blockIdx.x * 256 + threadIdx.x;
    if (i < N) out[i] += s2[batch[i]] + bnode[0];
}

// ---------------- host orchestration ----------------
extern "C" void kernel_launch(void* const* d_in, const int* in_sizes, int n_in,
                              void* d_out, int out_size) {
    const float* x      = (const float*)d_in[0];
    const int*   ei     = (const int*)d_in[1];
    const int*   batch  = (const int*)d_in[2];
    const int*   target = (const int*)d_in[3];
    const float* W1     = (const float*)d_in[4];
    const float* a1s    = (const float*)d_in[5];
    const float* a1d    = (const float*)d_in[6];
    const float* W2     = (const float*)d_in[8];
    const float* a2s    = (const float*)d_in[9];
    const float* a2d    = (const float*)d_in[10];
    const float* g1     = (const float*)d_in[12];
    const float* be1    = (const float*)d_in[13];
    const float* g2     = (const float*)d_in[14];
    const float* be2    = (const float*)d_in[15];
    const float* Wsh    = (const float*)d_in[16];
    const float* bsh    = (const float*)d_in[17];
    const float* Wnode  = (const float*)d_in[18];
    const float* bnode  = (const float*)d_in[19];
    const float* Wtype  = (const float*)d_in[20];
    const float* btype  = (const float*)d_in[21];
    const float* Wcrit  = (const float*)d_in[22];
    const float* bcrit  = (const float*)d_in[23];
    float* out = (float*)d_out;

    int N = in_sizes[2];
    int F = in_sizes[0] / N;
    int E = in_sizes[1] / 2;
    int Etot = E + N;

    float *bufA, *bufB, *als1, *ald1, *als2, *ald2;
    float *bnS, *bnQ, *sc1, *sh1, *sc2, *sh2, *poolS, *s2;
    int *cnt, *rowst, *cursor, *src_sorted;
    cudaGetSymbolAddress((void**)&bufA,  g_bufA);
    cudaGetSymbolAddress((void**)&bufB,  g_bufB);
    cudaGetSymbolAddress((void**)&als1,  g_als1);
    cudaGetSymbolAddress((void**)&ald1,  g_ald1);
    cudaGetSymbolAddress((void**)&als2,  g_als2);
    cudaGetSymbolAddress((void**)&ald2,  g_ald2);
    cudaGetSymbolAddress((void**)&cnt,   g_cnt);
    cudaGetSymbolAddress((void**)&rowst, g_rowst);
    cudaGetSymbolAddress((void**)&cursor, g_cursor);
    cudaGetSymbolAddress((void**)&src_sorted, g_src_sorted);
    cudaGetSymbolAddress((void**)&bnS,   g_bn_sum);
    cudaGetSymbolAddress((void**)&bnQ,   g_bn_sumsq);
    cudaGetSymbolAddress((void**)&sc1,   g_sc1);
    cudaGetSymbolAddress((void**)&sh1,   g_sh1);
    cudaGetSymbolAddress((void**)&sc2,   g_sc2);
    cudaGetSymbolAddress((void**)&sh2,   g_sh2);
    cudaGetSymbolAddress((void**)&poolS, g_pool_sum);
    cudaGetSymbolAddress((void**)&s2,    g_s2);

    // ---- zero init (async memsets; graph-capturable) ----
    cudaMemsetAsync(cnt,   0, (size_t)(N + 1) * sizeof(int));
    cudaMemsetAsync(als1,  0, (size_t)N * H1HEADS * sizeof(float));
    cudaMemsetAsync(ald1,  0, (size_t)N * H1HEADS * sizeof(float));
    cudaMemsetAsync(als2,  0, (size_t)N * sizeof(float));
    cudaMemsetAsync(ald2,  0, (size_t)N * sizeof(float));
    cudaMemsetAsync(poolS, 0, NGRAPHS * DFEAT * sizeof(float));
    cudaMemsetAsync(bnS,   0, DFEAT * sizeof(float));
    cudaMemsetAsync(bnQ,   0, DFEAT * sizeof(float));

    // ---- edge bucketing (shared by both layers) ----
    hist_k<<<cdiv(Etot, 256), 256>>>(ei, E, N, cnt);
    scan_k<<<1, SCAN_T>>>(cnt, rowst, N, Etot);
    cudaMemcpyAsync(cursor, rowst, (size_t)N * sizeof(int), cudaMemcpyDeviceToDevice);
    permute_k<<<cdiv(Etot, 256), 256>>>(ei, E, N, cursor, src_sorted);

    // ---- GAT layer 1: FFMA GEMM(128x64, +al1 epilogue) -> agg(+BN1 stats) ----
    {
        dim3 grid(DFEAT / 64, cdiv(N, TM));
        sgemm1_k<<<grid, 256>>>(x, W1, bufA, N, F, DFEAT, a1s, a1d, als1, ald1);
    }
    gat_agg1_k<<<cdiv(N, 8), 256>>>(rowst, src_sorted, bufA, als1, ald1, bufB, N, bnS, bnQ);
    bnprep_k<<<1, 256>>>(bnS, bnQ, g1, be1, sc1, sh1, N);

    // ---- GAT layer 2: tf32 MMA GEMM(128x128, BN1 on A, +al2) -> agg(+BN2 stats) -
    {
        dim3 grid(DFEAT / 128, cdiv(N, 128));
        mma_gemm_k<true, true><<<grid, 256>>>(bufB, W2, bufA, N, DFEAT, DFEAT,
                                              sc1, sh1, a2s, a2d, als2, ald2);
    }
    cudaMemsetAsync(bnS, 0, DFEAT * sizeof(float));
    cudaMemsetAsync(bnQ, 0, DFEAT * sizeof(float));
    gat_agg2_k<<<cdiv(N, 8), 256>>>(rowst, src_sorted, bufA, als2, ald2, bufB, N, bnS, bnQ);
    bnprep_k<<<1, 256>>>(bnS, bnQ, g2, be2, sc2, sh2, N);

    // ---- BN2 apply + nodescore dot + pool accumulation ----
    bn2_node_pool_k<<<cdiv(N, 8), 256>>>(bufB, sc2, sh2, Wnode, batch, poolS, out, N);

    // ---- heads + fixup ----
    heads_k<<<NGRAPHS, 256>>>(bufB, target, Wsh, bsh, Wnode, Wtype, btype, Wcrit, bcrit,
                              poolS, batch, s2, out, N);
    fixup_k<<<cdiv(N, 256), 256>>>(out, batch, s2, bnode, N);
}